// round 1
// baseline (speedup 1.0000x reference)
#include <cuda_runtime.h>

#define N_NODES 50000
#define N_EDGES 800000
#define C 128
#define NCLS 40

// ---------------- scratch (device globals; no allocation allowed) ----------
__device__ __align__(256) float g_deg_inv[N_NODES];
__device__ __align__(256) float g_agg[N_NODES * C];
__device__ __align__(256) float g_h1[N_NODES * C];
__device__ __align__(256) float g_h2[N_NODES * C];
__device__ int g_idx64;

// ---------------- dtype detection for edge_index (int32 vs int64) ----------
__global__ void detect_kernel(const unsigned int* ei) {
    // If int64: every odd 32-bit word (hi half) is 0. If int32: random indices.
    int zeros = 0;
    for (int i = 1; i < 128; i += 2) zeros += (ei[i] == 0u);
    g_idx64 = (zeros >= 32) ? 1 : 0;
}

__device__ __forceinline__ int load_edge(const void* ei, int pos, int is64) {
    return is64 ? (int)((const long long*)ei)[pos] : ((const int*)ei)[pos];
}

// ---------------- utility: zero a float buffer (float4 granularity) --------
__global__ void zero_kernel(float* p, int n4) {
    int i = blockIdx.x * blockDim.x + threadIdx.x;
    if (i < n4) ((float4*)p)[i] = make_float4(0.f, 0.f, 0.f, 0.f);
}

// ---------------- degree -----------------------------------------------
__global__ void deg_kernel(const void* ei) {
    int e = blockIdx.x * blockDim.x + threadIdx.x;
    if (e >= N_EDGES) return;
    int dst = load_edge(ei, N_EDGES + e, g_idx64);
    atomicAdd(&g_deg_inv[dst], 1.0f);
}

__global__ void deginv_kernel() {
    int i = blockIdx.x * blockDim.x + threadIdx.x;
    if (i < N_NODES) {
        float d = g_deg_inv[i];
        g_deg_inv[i] = (d > 0.f) ? (1.0f / d) : 0.0f;
    }
}

// ---------------- scatter-add aggregation: one warp per edge ---------------
__global__ void scatter_kernel(const void* __restrict__ ei,
                               const float* __restrict__ feat) {
    int wid = (blockIdx.x * blockDim.x + threadIdx.x) >> 5;
    int lane = threadIdx.x & 31;
    if (wid >= N_EDGES) return;
    int src = 0, dst = 0;
    if (lane == 0) {
        int is64 = g_idx64;
        src = load_edge(ei, wid, is64);
        dst = load_edge(ei, N_EDGES + wid, is64);
    }
    src = __shfl_sync(0xffffffffu, src, 0);
    dst = __shfl_sync(0xffffffffu, dst, 0);
    float4 v = *(const float4*)(feat + src * C + lane * 4);
    float* p = g_agg + dst * C + lane * 4;
    asm volatile("red.global.add.v4.f32 [%0], {%1,%2,%3,%4};"
                 :: "l"(p), "f"(v.x), "f"(v.y), "f"(v.z), "f"(v.w)
                 : "memory");
}

// ---------------- fused SAGE GEMM -------------------------------------
// out[n, c] = act( (agg[n,:]*deg_inv[n]) @ Wl + xin[n,:] @ Wr + b[c] )
// M=N_NODES, Nout=128, K=256 (virtual concat). BM=128, BN=128, BK=16.
// 256 threads, each computes an 8x8 micro-tile.
template <bool RELU>
__global__ void __launch_bounds__(256)
sage_gemm_kernel(const float* __restrict__ agg, const float* __restrict__ xin,
                 const float* __restrict__ Wl, const float* __restrict__ Wr,
                 const float* __restrict__ bias, float* __restrict__ out) {
    __shared__ float As[16][132];   // A transposed: As[k][m], padded stride
    __shared__ float Bs[16][128];   // B: Bs[k][c]

    const int t = threadIdx.x;
    const int tr = t >> 4;          // 0..15 -> row group
    const int tc = t & 15;          // 0..15 -> col group
    const int rowBase = blockIdx.x * 128;

    float acc[8][8];
#pragma unroll
    for (int i = 0; i < 8; i++)
#pragma unroll
        for (int j = 0; j < 8; j++) acc[i][j] = 0.f;

    for (int k0 = 0; k0 < 256; k0 += 16) {
        const bool first = (k0 < 128);
        const float* A = first ? agg : xin;
        const float* W = first ? Wl : Wr;
        const int kk0 = first ? k0 : (k0 - 128);

        // load A tile (128 rows x 16 k), transposed into As
#pragma unroll
        for (int l = 0; l < 2; l++) {
            int idx = t + l * 256;          // 0..511 float4 slots
            int m = idx >> 2;               // 0..127
            int q = idx & 3;                // which float4 of the 16 k's
            int gm = rowBase + m;
            float4 v = make_float4(0.f, 0.f, 0.f, 0.f);
            if (gm < N_NODES) {
                v = *(const float4*)(A + gm * C + kk0 + q * 4);
                if (first) {
                    float s = g_deg_inv[gm];
                    v.x *= s; v.y *= s; v.z *= s; v.w *= s;
                }
            }
            As[q * 4 + 0][m] = v.x;
            As[q * 4 + 1][m] = v.y;
            As[q * 4 + 2][m] = v.z;
            As[q * 4 + 3][m] = v.w;
        }
        // load B tile (16 k x 128 c)
#pragma unroll
        for (int l = 0; l < 2; l++) {
            int idx = t + l * 256;
            int k = idx >> 5;               // 0..15
            int c4 = (idx & 31) * 4;
            *(float4*)&Bs[k][c4] = *(const float4*)(W + (kk0 + k) * C + c4);
        }
        __syncthreads();

#pragma unroll
        for (int kk = 0; kk < 16; kk++) {
            float a[8], b[8];
            *(float4*)&a[0] = *(const float4*)&As[kk][tr * 8];
            *(float4*)&a[4] = *(const float4*)&As[kk][tr * 8 + 4];
            *(float4*)&b[0] = *(const float4*)&Bs[kk][tc * 8];
            *(float4*)&b[4] = *(const float4*)&Bs[kk][tc * 8 + 4];
#pragma unroll
            for (int i = 0; i < 8; i++)
#pragma unroll
                for (int j = 0; j < 8; j++) acc[i][j] += a[i] * b[j];
        }
        __syncthreads();
    }

    // epilogue
#pragma unroll
    for (int i = 0; i < 8; i++) {
        int gm = rowBase + tr * 8 + i;
        if (gm < N_NODES) {
#pragma unroll
            for (int j = 0; j < 8; j++) {
                int c = tc * 8 + j;
                float v = acc[i][j] + bias[c];
                if (RELU) v = fmaxf(v, 0.f);
                out[gm * C + c] = v;
            }
        }
    }
}

// ---------------- classifier: out[n, 0..39] = h[n,:] @ Wc + bc --------
__global__ void __launch_bounds__(256)
cls_kernel(const float* __restrict__ h, const float* __restrict__ Wc,
           const float* __restrict__ bc, float* __restrict__ out) {
    __shared__ float Ws[C * NCLS];   // 128*40 = 20KB
    __shared__ float Hs[32][C];      // 16KB
    int t = threadIdx.x;
    for (int i = t; i < C * NCLS; i += 256) Ws[i] = Wc[i];
    int nodeBase = blockIdx.x * 32;
    for (int i = t; i < 32 * C / 4; i += 256) {
        int r = i >> 5;
        int c4 = (i & 31) * 4;
        int n = nodeBase + r;
        float4 v = make_float4(0.f, 0.f, 0.f, 0.f);
        if (n < N_NODES) v = *(const float4*)(h + n * C + c4);
        *(float4*)&Hs[r][c4] = v;
    }
    __syncthreads();
    for (int o = t; o < 32 * NCLS; o += 256) {
        int r = o / NCLS, c = o % NCLS;
        int n = nodeBase + r;
        if (n >= N_NODES) continue;
        float acc = bc[c];
#pragma unroll 8
        for (int k = 0; k < C; k++) acc += Hs[r][k] * Ws[k * NCLS + c];
        out[n * NCLS + c] = acc;
    }
}

// ---------------- launch ----------------------------------------------
extern "C" void kernel_launch(void* const* d_in, const int* in_sizes, int n_in,
                              void* d_out, int out_size) {
    (void)in_sizes; (void)n_in; (void)out_size;
    const float* x    = (const float*)d_in[0];
    const void*  ei   = d_in[1];
    const float* Wl1  = (const float*)d_in[2];
    const float* Wr1  = (const float*)d_in[3];
    const float* b1   = (const float*)d_in[4];
    const float* Wl2  = (const float*)d_in[5];
    const float* Wr2  = (const float*)d_in[6];
    const float* b2   = (const float*)d_in[7];
    const float* Wc   = (const float*)d_in[8];
    const float* bc   = (const float*)d_in[9];
    float* out = (float*)d_out;

    float* deg_inv_p; cudaGetSymbolAddress((void**)&deg_inv_p, g_deg_inv);
    float* agg_p;     cudaGetSymbolAddress((void**)&agg_p, g_agg);
    float* h1_p;      cudaGetSymbolAddress((void**)&h1_p, g_h1);
    float* h2_p;      cudaGetSymbolAddress((void**)&h2_p, g_h2);

    const int aggN4 = N_NODES * C / 4;
    const int degN4 = N_NODES / 4;

    detect_kernel<<<1, 1>>>((const unsigned int*)ei);

    // degree
    zero_kernel<<<(degN4 + 255) / 256, 256>>>(deg_inv_p, degN4);
    deg_kernel<<<(N_EDGES + 255) / 256, 256>>>(ei);
    deginv_kernel<<<(N_NODES + 255) / 256, 256>>>();

    // layer 1
    zero_kernel<<<(aggN4 + 255) / 256, 256>>>(agg_p, aggN4);
    scatter_kernel<<<(N_EDGES * 32) / 256, 256>>>(ei, x);
    sage_gemm_kernel<true><<<(N_NODES + 127) / 128, 256>>>(agg_p, x, Wl1, Wr1, b1, h1_p);

    // layer 2
    zero_kernel<<<(aggN4 + 255) / 256, 256>>>(agg_p, aggN4);
    scatter_kernel<<<(N_EDGES * 32) / 256, 256>>>(ei, h1_p);
    sage_gemm_kernel<true><<<(N_NODES + 127) / 128, 256>>>(agg_p, h1_p, Wl2, Wr2, b2, h2_p);

    // classifier
    cls_kernel<<<(N_NODES + 31) / 32, 256>>>(h2_p, Wc, bc, out);
}

// round 4
// speedup vs baseline: 1.4149x; 1.4149x over previous
#include <cuda_runtime.h>
#include <cuda_bf16.h>
#include <cstdint>

#define N_NODES 50000
#define N_EDGES 800000
#define C 128
#define NCLS 40

// ======================= scratch (no allocation allowed) ====================
__device__ __align__(256) float g_deg_inv[N_NODES];
__device__ __align__(256) float g_agg[N_NODES * C];
__device__ __align__(256) float g_h1[N_NODES * C];
__device__ __align__(256) float g_h2[N_NODES * C];
// Weight images: [256 k][128 n] bf16, plain row-major, hi/lo split, per layer.
__device__ __align__(256) __nv_bfloat16 g_B1hi[256 * 128];
__device__ __align__(256) __nv_bfloat16 g_B1lo[256 * 128];
__device__ __align__(256) __nv_bfloat16 g_B2hi[256 * 128];
__device__ __align__(256) __nv_bfloat16 g_B2lo[256 * 128];
__device__ int g_idx64;

// ======================= helpers =======================
__device__ __forceinline__ uint32_t smem_u32(const void* p) {
    uint32_t a;
    asm("{ .reg .u64 t; cvta.to.shared.u64 t, %1; cvt.u32.u64 %0, t; }"
        : "=r"(a) : "l"(p));
    return a;
}
__device__ __forceinline__ void ldsm_x4(uint32_t& r0, uint32_t& r1,
                                        uint32_t& r2, uint32_t& r3, uint32_t addr) {
    asm volatile("ldmatrix.sync.aligned.m8n8.x4.shared.b16 {%0,%1,%2,%3}, [%4];"
                 : "=r"(r0), "=r"(r1), "=r"(r2), "=r"(r3) : "r"(addr));
}
__device__ __forceinline__ void ldsm_x4_t(uint32_t& r0, uint32_t& r1,
                                          uint32_t& r2, uint32_t& r3, uint32_t addr) {
    asm volatile("ldmatrix.sync.aligned.m8n8.x4.trans.shared.b16 {%0,%1,%2,%3}, [%4];"
                 : "=r"(r0), "=r"(r1), "=r"(r2), "=r"(r3) : "r"(addr));
}
__device__ __forceinline__ void mma_bf16(float* c, const uint32_t* a, const uint32_t* b) {
    asm volatile(
        "mma.sync.aligned.m16n8k16.row.col.f32.bf16.bf16.f32 "
        "{%0,%1,%2,%3}, {%4,%5,%6,%7}, {%8,%9}, {%0,%1,%2,%3};"
        : "+f"(c[0]), "+f"(c[1]), "+f"(c[2]), "+f"(c[3])
        : "r"(a[0]), "r"(a[1]), "r"(a[2]), "r"(a[3]), "r"(b[0]), "r"(b[1]));
}

// ======================= small kernels =======================
__global__ void detect_kernel(const unsigned int* ei) {
    int zeros = 0;
    for (int i = 1; i < 128; i += 2) zeros += (ei[i] == 0u);
    g_idx64 = (zeros >= 32) ? 1 : 0;
}
__device__ __forceinline__ int load_edge(const void* ei, int pos, int is64) {
    return is64 ? (int)((const long long*)ei)[pos] : ((const int*)ei)[pos];
}
__global__ void zero_kernel(float* p, int n4) {
    int i = blockIdx.x * blockDim.x + threadIdx.x;
    if (i < n4) ((float4*)p)[i] = make_float4(0.f, 0.f, 0.f, 0.f);
}
__global__ void deg_kernel(const void* ei) {
    int e = blockIdx.x * blockDim.x + threadIdx.x;
    if (e >= N_EDGES) return;
    int dst = load_edge(ei, N_EDGES + e, g_idx64);
    atomicAdd(&g_deg_inv[dst], 1.0f);
}
__global__ void deginv_kernel() {
    int i = blockIdx.x * blockDim.x + threadIdx.x;
    if (i < N_NODES) {
        float d = g_deg_inv[i];
        g_deg_inv[i] = (d > 0.f) ? (1.0f / d) : 0.0f;
    }
}

// Weight prep: B[k][n] = W[k mod 128][n] from Wl (k<128) else Wr; bf16 hi/lo split.
__global__ void prep_w_kernel(const float* __restrict__ Wl1, const float* __restrict__ Wr1,
                              const float* __restrict__ Wl2, const float* __restrict__ Wr2) {
    int idx = blockIdx.x * blockDim.x + threadIdx.x;  // 2 * 256 * 128
    if (idx >= 2 * 256 * 128) return;
    int layer = idx >> 15;
    int rem = idx & 32767;
    int k = rem >> 7;
    int n = rem & 127;
    const float* W = (layer == 0) ? ((k < 128) ? Wl1 : Wr1) : ((k < 128) ? Wl2 : Wr2);
    float v = W[(k & 127) * 128 + n];
    __nv_bfloat16 hi = __float2bfloat16(v);
    __nv_bfloat16 lo = __float2bfloat16(v - __bfloat162float(hi));
    (layer ? g_B2hi : g_B1hi)[k * 128 + n] = hi;
    (layer ? g_B2lo : g_B1lo)[k * 128 + n] = lo;
}

// ======================= scatter-add: one warp per edge =======================
__global__ void scatter_kernel(const void* __restrict__ ei,
                               const float* __restrict__ feat) {
    int wid = (blockIdx.x * blockDim.x + threadIdx.x) >> 5;
    int lane = threadIdx.x & 31;
    if (wid >= N_EDGES) return;
    int src = 0, dst = 0;
    if (lane == 0) {
        int is64 = g_idx64;
        src = load_edge(ei, wid, is64);
        dst = load_edge(ei, N_EDGES + wid, is64);
    }
    src = __shfl_sync(0xffffffffu, src, 0);
    dst = __shfl_sync(0xffffffffu, dst, 0);
    float4 v = *(const float4*)(feat + src * C + lane * 4);
    float* p = g_agg + dst * C + lane * 4;
    asm volatile("red.global.add.v4.f32 [%0], {%1,%2,%3,%4};"
                 :: "l"(p), "f"(v.x), "f"(v.y), "f"(v.z), "f"(v.w)
                 : "memory");
}

// ======================= HMMA SAGE GEMM =======================
// out[m, :] = relu( [agg[m]*deginv | x[m]] @ B + bias ), bf16 2-split, 3 terms.
// BM=128, BN=128, BK=64, 8 warps (2 m x 4 n), warp tile 64x32.
#define A_STRIDE 72   // bf16 elements per A smem row (64 + 8 pad)
#define B_STRIDE 136  // bf16 elements per B smem row (128 + 8 pad)
#define SM_AH 0
#define SM_AL (128 * A_STRIDE * 2)
#define SM_BH (2 * 128 * A_STRIDE * 2)
#define SM_BL (2 * 128 * A_STRIDE * 2 + 64 * B_STRIDE * 2)
#define SM_TOTAL (2 * 128 * A_STRIDE * 2 + 2 * 64 * B_STRIDE * 2)  // 71680 B

__global__ void __launch_bounds__(256)
sage_gemm_mma(const float* __restrict__ agg, const float* __restrict__ xin,
              const __nv_bfloat16* __restrict__ Bhi, const __nv_bfloat16* __restrict__ Blo,
              const float* __restrict__ bias, float* __restrict__ out) {
    extern __shared__ unsigned char smem[];
    const uint32_t sbase = smem_u32(smem);
    const int t = threadIdx.x;
    const int wid = t >> 5, lane = t & 31;
    const int warp_m = wid >> 2;      // 0..1 -> 64-row slab
    const int warp_n = wid & 3;       // 0..3 -> 32-col slab
    const int rowBase = blockIdx.x * 128;

    float acc[4][4][4];
#pragma unroll
    for (int i = 0; i < 4; i++)
#pragma unroll
        for (int j = 0; j < 4; j++)
#pragma unroll
            for (int r = 0; r < 4; r++) acc[i][j][r] = 0.f;

    // per-lane ldmatrix address components (element offsets)
    const int a_row = warp_m * 64 + (lane & 15);       // + i*16
    const int a_col = (lane >> 4) * 8;                 // + kk
    const int b_row = (lane & 7) + (lane & 8);         // + kk
    const int b_col = warp_n * 32 + (lane >> 4) * 8;   // + jj*16

    for (int chunk = 0; chunk < 4; ++chunk) {
        const int k0 = chunk * 64;
        const bool isAgg = (chunk < 2);
        const float* src = isAgg ? agg : xin;
        const int koff = isAgg ? k0 : (k0 - 128);

        // ---- fill A hi/lo: 128 rows x 64 k (fp32 load + split) ----
#pragma unroll
        for (int it = 0; it < 8; ++it) {
            int idx = it * 256 + t;        // 2048 float4 slots
            int row = idx >> 4;
            int q = idx & 15;              // float4 within row
            int gm = rowBase + row;
            float4 v = make_float4(0.f, 0.f, 0.f, 0.f);
            if (gm < N_NODES) {
                v = *(const float4*)(src + (size_t)gm * C + koff + q * 4);
                if (isAgg) {
                    float s = g_deg_inv[gm];
                    v.x *= s; v.y *= s; v.z *= s; v.w *= s;
                }
            }
            __nv_bfloat16 hx = __float2bfloat16(v.x), hy = __float2bfloat16(v.y);
            __nv_bfloat16 hz = __float2bfloat16(v.z), hw = __float2bfloat16(v.w);
            __nv_bfloat16 lx = __float2bfloat16(v.x - __bfloat162float(hx));
            __nv_bfloat16 ly = __float2bfloat16(v.y - __bfloat162float(hy));
            __nv_bfloat16 lz = __float2bfloat16(v.z - __bfloat162float(hz));
            __nv_bfloat16 lw = __float2bfloat16(v.w - __bfloat162float(hw));
            uint32_t h0 = ((uint32_t)__bfloat16_as_ushort(hy) << 16) | __bfloat16_as_ushort(hx);
            uint32_t h1 = ((uint32_t)__bfloat16_as_ushort(hw) << 16) | __bfloat16_as_ushort(hz);
            uint32_t l0 = ((uint32_t)__bfloat16_as_ushort(ly) << 16) | __bfloat16_as_ushort(lx);
            uint32_t l1 = ((uint32_t)__bfloat16_as_ushort(lw) << 16) | __bfloat16_as_ushort(lz);
            uint32_t off = (uint32_t)(row * A_STRIDE + q * 4) * 2;
            *(uint32_t*)(smem + SM_AH + off) = h0;
            *(uint32_t*)(smem + SM_AH + off + 4) = h1;
            *(uint32_t*)(smem + SM_AL + off) = l0;
            *(uint32_t*)(smem + SM_AL + off + 4) = l1;
        }
        // ---- fill B hi/lo: 64 k-rows x 128 n, both splits ----
        // 64 rows x 16 uint4/row x 2 splits = 2048 uint4 slots  (round-3 fix)
#pragma unroll
        for (int it = 0; it < 8; ++it) {
            int idx = it * 256 + t;          // 0..2047
            int split = idx >> 10;           // 0 = hi, 1 = lo
            int rem = idx & 1023;
            int r = rem >> 4;                // 0..63 (k-row)
            int c8 = (rem & 15) * 8;         // bf16 col 0..120
            const __nv_bfloat16* g = split ? Blo : Bhi;
            uint4 v = *(const uint4*)(g + (size_t)(k0 + r) * 128 + c8);
            uint32_t off = (split ? SM_BL : SM_BH) + (uint32_t)(r * B_STRIDE + c8) * 2;
            *(uint4*)(smem + off) = v;
        }
        __syncthreads();

        // ---- compute: 4 k-steps of 16 ----
#pragma unroll
        for (int ks = 0; ks < 4; ++ks) {
            const int kk = ks * 16;
            uint32_t ah[4][4], al[4][4], bh[4][2], bl[4][2];
#pragma unroll
            for (int i = 0; i < 4; ++i) {
                uint32_t addr = sbase + SM_AH +
                    (uint32_t)((a_row + i * 16) * A_STRIDE + kk + a_col) * 2;
                ldsm_x4(ah[i][0], ah[i][1], ah[i][2], ah[i][3], addr);
                ldsm_x4(al[i][0], al[i][1], al[i][2], al[i][3], addr + (SM_AL - SM_AH));
            }
#pragma unroll
            for (int jj = 0; jj < 2; ++jj) {
                uint32_t addr = sbase + SM_BH +
                    (uint32_t)((kk + b_row) * B_STRIDE + b_col + jj * 16) * 2;
                ldsm_x4_t(bh[jj * 2][0], bh[jj * 2][1], bh[jj * 2 + 1][0], bh[jj * 2 + 1][1], addr);
                ldsm_x4_t(bl[jj * 2][0], bl[jj * 2][1], bl[jj * 2 + 1][0], bl[jj * 2 + 1][1],
                          addr + (SM_BL - SM_BH));
            }
#pragma unroll
            for (int i = 0; i < 4; ++i)
#pragma unroll
                for (int j = 0; j < 4; ++j) {
                    mma_bf16(acc[i][j], ah[i], bh[j]);
                    mma_bf16(acc[i][j], ah[i], bl[j]);
                    mma_bf16(acc[i][j], al[i], bh[j]);
                }
        }
        __syncthreads();
    }

    // ---- epilogue: bias + relu + store fp32 ----
    const int er = lane >> 2;          // 0..7
    const int ec = (lane & 3) * 2;     // 0,2,4,6
#pragma unroll
    for (int i = 0; i < 4; ++i) {
        int gm0 = rowBase + warp_m * 64 + i * 16 + er;
#pragma unroll
        for (int j = 0; j < 4; ++j) {
            int col = warp_n * 32 + j * 8 + ec;
            float b0 = bias[col], b1 = bias[col + 1];
            if (gm0 < N_NODES) {
                float2 o;
                o.x = fmaxf(acc[i][j][0] + b0, 0.f);
                o.y = fmaxf(acc[i][j][1] + b1, 0.f);
                *(float2*)(out + (size_t)gm0 * C + col) = o;
            }
            if (gm0 + 8 < N_NODES) {
                float2 o;
                o.x = fmaxf(acc[i][j][2] + b0, 0.f);
                o.y = fmaxf(acc[i][j][3] + b1, 0.f);
                *(float2*)(out + (size_t)(gm0 + 8) * C + col) = o;
            }
        }
    }
}

// ======================= classifier =======================
__global__ void __launch_bounds__(256)
cls_kernel(const float* __restrict__ h, const float* __restrict__ Wc,
           const float* __restrict__ bc, float* __restrict__ out) {
    __shared__ float Ws[C * NCLS];
    __shared__ float Hs[32][C];
    int t = threadIdx.x;
    for (int i = t; i < C * NCLS; i += 256) Ws[i] = Wc[i];
    int nodeBase = blockIdx.x * 32;
    for (int i = t; i < 32 * C / 4; i += 256) {
        int r = i >> 5;
        int c4 = (i & 31) * 4;
        int n = nodeBase + r;
        float4 v = make_float4(0.f, 0.f, 0.f, 0.f);
        if (n < N_NODES) v = *(const float4*)(h + n * C + c4);
        *(float4*)&Hs[r][c4] = v;
    }
    __syncthreads();
    for (int o = t; o < 32 * NCLS; o += 256) {
        int r = o / NCLS, c = o % NCLS;
        int n = nodeBase + r;
        if (n >= N_NODES) continue;
        float acc = bc[c];
#pragma unroll 8
        for (int k = 0; k < C; k++) acc += Hs[r][k] * Ws[k * NCLS + c];
        out[n * NCLS + c] = acc;
    }
}

// ======================= launch =======================
extern "C" void kernel_launch(void* const* d_in, const int* in_sizes, int n_in,
                              void* d_out, int out_size) {
    (void)in_sizes; (void)n_in; (void)out_size;
    const float* x   = (const float*)d_in[0];
    const void*  ei  = d_in[1];
    const float* Wl1 = (const float*)d_in[2];
    const float* Wr1 = (const float*)d_in[3];
    const float* b1  = (const float*)d_in[4];
    const float* Wl2 = (const float*)d_in[5];
    const float* Wr2 = (const float*)d_in[6];
    const float* b2  = (const float*)d_in[7];
    const float* Wc  = (const float*)d_in[8];
    const float* bc  = (const float*)d_in[9];
    float* out = (float*)d_out;

    float* deg_inv_p; cudaGetSymbolAddress((void**)&deg_inv_p, g_deg_inv);
    float* agg_p;     cudaGetSymbolAddress((void**)&agg_p, g_agg);
    float* h1_p;      cudaGetSymbolAddress((void**)&h1_p, g_h1);
    float* h2_p;      cudaGetSymbolAddress((void**)&h2_p, g_h2);
    __nv_bfloat16 *b1hi, *b1lo, *b2hi, *b2lo;
    cudaGetSymbolAddress((void**)&b1hi, g_B1hi);
    cudaGetSymbolAddress((void**)&b1lo, g_B1lo);
    cudaGetSymbolAddress((void**)&b2hi, g_B2hi);
    cudaGetSymbolAddress((void**)&b2lo, g_B2lo);

    cudaFuncSetAttribute(sage_gemm_mma, cudaFuncAttributeMaxDynamicSharedMemorySize, SM_TOTAL);

    const int aggN4 = N_NODES * C / 4;
    const int degN4 = N_NODES / 4;
    const int nBlocks = (N_NODES + 127) / 128;  // 391

    detect_kernel<<<1, 1>>>((const unsigned int*)ei);
    prep_w_kernel<<<256, 256>>>(Wl1, Wr1, Wl2, Wr2);

    zero_kernel<<<(degN4 + 255) / 256, 256>>>(deg_inv_p, degN4);
    deg_kernel<<<(N_EDGES + 255) / 256, 256>>>(ei);
    deginv_kernel<<<(N_NODES + 255) / 256, 256>>>();

    // layer 1
    zero_kernel<<<(aggN4 + 255) / 256, 256>>>(agg_p, aggN4);
    scatter_kernel<<<(N_EDGES * 32) / 256, 256>>>(ei, x);
    sage_gemm_mma<<<nBlocks, 256, SM_TOTAL>>>(agg_p, x, b1hi, b1lo, b1, h1_p);

    // layer 2
    zero_kernel<<<(aggN4 + 255) / 256, 256>>>(agg_p, aggN4);
    scatter_kernel<<<(N_EDGES * 32) / 256, 256>>>(ei, h1_p);
    sage_gemm_mma<<<nBlocks, 256, SM_TOTAL>>>(agg_p, h1_p, b2hi, b2lo, b2, h2_p);

    // classifier
    cls_kernel<<<(N_NODES + 31) / 32, 256>>>(h2_p, Wc, bc, out);
}

// round 5
// speedup vs baseline: 1.4820x; 1.0474x over previous
#include <cuda_runtime.h>
#include <cuda_bf16.h>
#include <cstdint>

#define N_NODES 50000
#define N_EDGES 800000
#define C 128
#define NCLS 40

// ======================= scratch (no allocation allowed) ====================
__device__ __align__(256) float g_deg_inv[N_NODES];
__device__ __align__(256) int   g_deg[N_NODES];
__device__ __align__(256) int   g_off[N_NODES + 1];
__device__ __align__(256) int   g_cursor[N_NODES];
__device__ __align__(256) int   g_csr_src[N_EDGES];
__device__ __align__(256) float g_agg[N_NODES * C];
__device__ __align__(256) float g_h1[N_NODES * C];
__device__ __align__(256) float g_h2[N_NODES * C];
// Weight images: [256 k][128 n] bf16, row-major, hi/lo split, per layer.
__device__ __align__(256) __nv_bfloat16 g_B1hi[256 * 128];
__device__ __align__(256) __nv_bfloat16 g_B1lo[256 * 128];
__device__ __align__(256) __nv_bfloat16 g_B2hi[256 * 128];
__device__ __align__(256) __nv_bfloat16 g_B2lo[256 * 128];
__device__ int g_idx64;

// ======================= helpers =======================
__device__ __forceinline__ uint32_t smem_u32(const void* p) {
    uint32_t a;
    asm("{ .reg .u64 t; cvta.to.shared.u64 t, %1; cvt.u32.u64 %0, t; }"
        : "=r"(a) : "l"(p));
    return a;
}
__device__ __forceinline__ void ldsm_x4(uint32_t& r0, uint32_t& r1,
                                        uint32_t& r2, uint32_t& r3, uint32_t addr) {
    asm volatile("ldmatrix.sync.aligned.m8n8.x4.shared.b16 {%0,%1,%2,%3}, [%4];"
                 : "=r"(r0), "=r"(r1), "=r"(r2), "=r"(r3) : "r"(addr));
}
__device__ __forceinline__ void ldsm_x4_t(uint32_t& r0, uint32_t& r1,
                                          uint32_t& r2, uint32_t& r3, uint32_t addr) {
    asm volatile("ldmatrix.sync.aligned.m8n8.x4.trans.shared.b16 {%0,%1,%2,%3}, [%4];"
                 : "=r"(r0), "=r"(r1), "=r"(r2), "=r"(r3) : "r"(addr));
}
__device__ __forceinline__ void mma_bf16(float* c, const uint32_t* a, const uint32_t* b) {
    asm volatile(
        "mma.sync.aligned.m16n8k16.row.col.f32.bf16.bf16.f32 "
        "{%0,%1,%2,%3}, {%4,%5,%6,%7}, {%8,%9}, {%0,%1,%2,%3};"
        : "+f"(c[0]), "+f"(c[1]), "+f"(c[2]), "+f"(c[3])
        : "r"(a[0]), "r"(a[1]), "r"(a[2]), "r"(a[3]), "r"(b[0]), "r"(b[1]));
}

// ======================= small kernels =======================
__global__ void detect_kernel(const unsigned int* ei) {
    int zeros = 0;
    for (int i = 1; i < 128; i += 2) zeros += (ei[i] == 0u);
    g_idx64 = (zeros >= 32) ? 1 : 0;
}
__device__ __forceinline__ int load_edge(const void* ei, int pos, int is64) {
    return is64 ? (int)((const long long*)ei)[pos] : ((const int*)ei)[pos];
}
__global__ void zero_int_kernel(int* p, int n) {
    int i = blockIdx.x * blockDim.x + threadIdx.x;
    if (i < n) p[i] = 0;
}
__global__ void deg_kernel(const void* ei) {
    int e = blockIdx.x * blockDim.x + threadIdx.x;
    if (e >= N_EDGES) return;
    int dst = load_edge(ei, N_EDGES + e, g_idx64);
    atomicAdd(&g_deg[dst], 1);
}

// Single-block exclusive scan over g_deg -> g_off/g_cursor; also deg_inv.
#define SCAN_T 1024
__global__ void __launch_bounds__(SCAN_T)
scan_kernel() {
    __shared__ int part[SCAN_T];
    const int t = threadIdx.x;
    const int CH = (N_NODES + SCAN_T - 1) / SCAN_T;   // 49
    const int lo = t * CH;
    const int hi = (lo + CH < N_NODES) ? lo + CH : N_NODES;
    int s = 0;
    for (int i = lo; i < hi; i++) s += g_deg[i];
    part[t] = s;
    __syncthreads();
    for (int off = 1; off < SCAN_T; off <<= 1) {
        int v = 0;
        if (t >= off) v = part[t - off];
        __syncthreads();
        if (t >= off) part[t] += v;
        __syncthreads();
    }
    int run = (t == 0) ? 0 : part[t - 1];
    for (int i = lo; i < hi; i++) {
        int d = g_deg[i];
        g_off[i] = run;
        g_cursor[i] = run;
        g_deg_inv[i] = (d > 0) ? (1.0f / (float)d) : 0.0f;
        run += d;
    }
    if (t == SCAN_T - 1) g_off[N_NODES] = run;
}

__global__ void csrfill_kernel(const void* __restrict__ ei) {
    int e = blockIdx.x * blockDim.x + threadIdx.x;
    if (e >= N_EDGES) return;
    int is64 = g_idx64;
    int src = load_edge(ei, e, is64);
    int dst = load_edge(ei, N_EDGES + e, is64);
    int pos = atomicAdd(&g_cursor[dst], 1);
    g_csr_src[pos] = src;
}

// Weight prep: B[k][n] = W[k mod 128][n] from Wl (k<128) else Wr; bf16 hi/lo split.
__global__ void prep_w_kernel(const float* __restrict__ Wl1, const float* __restrict__ Wr1,
                              const float* __restrict__ Wl2, const float* __restrict__ Wr2) {
    int idx = blockIdx.x * blockDim.x + threadIdx.x;  // 2 * 256 * 128
    if (idx >= 2 * 256 * 128) return;
    int layer = idx >> 15;
    int rem = idx & 32767;
    int k = rem >> 7;
    int n = rem & 127;
    const float* W = (layer == 0) ? ((k < 128) ? Wl1 : Wr1) : ((k < 128) ? Wl2 : Wr2);
    float v = W[(k & 127) * 128 + n];
    __nv_bfloat16 hi = __float2bfloat16(v);
    __nv_bfloat16 lo = __float2bfloat16(v - __bfloat162float(hi));
    (layer ? g_B2hi : g_B1hi)[k * 128 + n] = hi;
    (layer ? g_B2lo : g_B1lo)[k * 128 + n] = lo;
}

// ======================= CSR gather-mean: one warp per node =================
__global__ void __launch_bounds__(256)
gather_kernel(const float* __restrict__ feat, float* __restrict__ agg) {
    int node = (blockIdx.x * blockDim.x + threadIdx.x) >> 5;
    int lane = threadIdx.x & 31;
    if (node >= N_NODES) return;
    int start = g_off[node];
    int end = g_off[node + 1];
    float4 acc = make_float4(0.f, 0.f, 0.f, 0.f);
    for (int e = start; e < end; ++e) {
        int src = __ldg(&g_csr_src[e]);
        float4 v = *(const float4*)(feat + (size_t)src * C + lane * 4);
        acc.x += v.x; acc.y += v.y; acc.z += v.z; acc.w += v.w;
    }
    float s = g_deg_inv[node];
    acc.x *= s; acc.y *= s; acc.z *= s; acc.w *= s;
    *(float4*)(agg + (size_t)node * C + lane * 4) = acc;
}

// ======================= HMMA SAGE GEMM =======================
// out[m, :] = relu( [agg[m] | x[m]] @ B + bias ), bf16 2-split, 3 terms.
// BM=128, BN=128, BK=64, 8 warps (2 m x 4 n), warp tile 64x32.
#define A_STRIDE 72   // bf16 elements per A smem row (64 + 8 pad)
#define B_STRIDE 136  // bf16 elements per B smem row (128 + 8 pad)
#define SM_AH 0
#define SM_AL (128 * A_STRIDE * 2)
#define SM_BH (2 * 128 * A_STRIDE * 2)
#define SM_BL (2 * 128 * A_STRIDE * 2 + 64 * B_STRIDE * 2)
#define SM_TOTAL (2 * 128 * A_STRIDE * 2 + 2 * 64 * B_STRIDE * 2)  // 71680 B

__global__ void __launch_bounds__(256)
sage_gemm_mma(const float* __restrict__ agg, const float* __restrict__ xin,
              const __nv_bfloat16* __restrict__ Bhi, const __nv_bfloat16* __restrict__ Blo,
              const float* __restrict__ bias, float* __restrict__ out) {
    extern __shared__ unsigned char smem[];
    const uint32_t sbase = smem_u32(smem);
    const int t = threadIdx.x;
    const int wid = t >> 5, lane = t & 31;
    const int warp_m = wid >> 2;      // 0..1 -> 64-row slab
    const int warp_n = wid & 3;       // 0..3 -> 32-col slab
    const int rowBase = blockIdx.x * 128;

    float acc[4][4][4];
#pragma unroll
    for (int i = 0; i < 4; i++)
#pragma unroll
        for (int j = 0; j < 4; j++)
#pragma unroll
            for (int r = 0; r < 4; r++) acc[i][j][r] = 0.f;

    const int a_row = warp_m * 64 + (lane & 15);
    const int a_col = (lane >> 4) * 8;
    const int b_row = (lane & 7) + (lane & 8);
    const int b_col = warp_n * 32 + (lane >> 4) * 8;

    for (int chunk = 0; chunk < 4; ++chunk) {
        const int k0 = chunk * 64;
        const bool isAgg = (chunk < 2);
        const float* src = isAgg ? agg : xin;
        const int koff = isAgg ? k0 : (k0 - 128);

        // ---- fill A hi/lo: 128 rows x 64 k ----
#pragma unroll
        for (int it = 0; it < 8; ++it) {
            int idx = it * 256 + t;
            int row = idx >> 4;
            int q = idx & 15;
            int gm = rowBase + row;
            float4 v = make_float4(0.f, 0.f, 0.f, 0.f);
            if (gm < N_NODES)
                v = *(const float4*)(src + (size_t)gm * C + koff + q * 4);
            __nv_bfloat16 hx = __float2bfloat16(v.x), hy = __float2bfloat16(v.y);
            __nv_bfloat16 hz = __float2bfloat16(v.z), hw = __float2bfloat16(v.w);
            __nv_bfloat16 lx = __float2bfloat16(v.x - __bfloat162float(hx));
            __nv_bfloat16 ly = __float2bfloat16(v.y - __bfloat162float(hy));
            __nv_bfloat16 lz = __float2bfloat16(v.z - __bfloat162float(hz));
            __nv_bfloat16 lw = __float2bfloat16(v.w - __bfloat162float(hw));
            uint32_t h0 = ((uint32_t)__bfloat16_as_ushort(hy) << 16) | __bfloat16_as_ushort(hx);
            uint32_t h1 = ((uint32_t)__bfloat16_as_ushort(hw) << 16) | __bfloat16_as_ushort(hz);
            uint32_t l0 = ((uint32_t)__bfloat16_as_ushort(ly) << 16) | __bfloat16_as_ushort(lx);
            uint32_t l1 = ((uint32_t)__bfloat16_as_ushort(lw) << 16) | __bfloat16_as_ushort(lz);
            uint32_t off = (uint32_t)(row * A_STRIDE + q * 4) * 2;
            *(uint32_t*)(smem + SM_AH + off) = h0;
            *(uint32_t*)(smem + SM_AH + off + 4) = h1;
            *(uint32_t*)(smem + SM_AL + off) = l0;
            *(uint32_t*)(smem + SM_AL + off + 4) = l1;
        }
        // ---- fill B hi/lo: 64 k-rows x 128 n, both splits (2048 uint4) ----
#pragma unroll
        for (int it = 0; it < 8; ++it) {
            int idx = it * 256 + t;
            int split = idx >> 10;
            int rem = idx & 1023;
            int r = rem >> 4;
            int c8 = (rem & 15) * 8;
            const __nv_bfloat16* g = split ? Blo : Bhi;
            uint4 v = *(const uint4*)(g + (size_t)(k0 + r) * 128 + c8);
            uint32_t off = (split ? SM_BL : SM_BH) + (uint32_t)(r * B_STRIDE + c8) * 2;
            *(uint4*)(smem + off) = v;
        }
        __syncthreads();

        // ---- compute: 4 k-steps of 16 ----
#pragma unroll
        for (int ks = 0; ks < 4; ++ks) {
            const int kk = ks * 16;
            uint32_t ah[4][4], al[4][4], bh[4][2], bl[4][2];
#pragma unroll
            for (int i = 0; i < 4; ++i) {
                uint32_t addr = sbase + SM_AH +
                    (uint32_t)((a_row + i * 16) * A_STRIDE + kk + a_col) * 2;
                ldsm_x4(ah[i][0], ah[i][1], ah[i][2], ah[i][3], addr);
                ldsm_x4(al[i][0], al[i][1], al[i][2], al[i][3], addr + (SM_AL - SM_AH));
            }
#pragma unroll
            for (int jj = 0; jj < 2; ++jj) {
                uint32_t addr = sbase + SM_BH +
                    (uint32_t)((kk + b_row) * B_STRIDE + b_col + jj * 16) * 2;
                ldsm_x4_t(bh[jj * 2][0], bh[jj * 2][1], bh[jj * 2 + 1][0], bh[jj * 2 + 1][1], addr);
                ldsm_x4_t(bl[jj * 2][0], bl[jj * 2][1], bl[jj * 2 + 1][0], bl[jj * 2 + 1][1],
                          addr + (SM_BL - SM_BH));
            }
#pragma unroll
            for (int i = 0; i < 4; ++i)
#pragma unroll
                for (int j = 0; j < 4; ++j) {
                    mma_bf16(acc[i][j], ah[i], bh[j]);
                    mma_bf16(acc[i][j], ah[i], bl[j]);
                    mma_bf16(acc[i][j], al[i], bh[j]);
                }
        }
        __syncthreads();
    }

    // ---- epilogue: bias + relu + store fp32 ----
    const int er = lane >> 2;
    const int ec = (lane & 3) * 2;
#pragma unroll
    for (int i = 0; i < 4; ++i) {
        int gm0 = rowBase + warp_m * 64 + i * 16 + er;
#pragma unroll
        for (int j = 0; j < 4; ++j) {
            int col = warp_n * 32 + j * 8 + ec;
            float b0 = bias[col], b1 = bias[col + 1];
            if (gm0 < N_NODES) {
                float2 o;
                o.x = fmaxf(acc[i][j][0] + b0, 0.f);
                o.y = fmaxf(acc[i][j][1] + b1, 0.f);
                *(float2*)(out + (size_t)gm0 * C + col) = o;
            }
            if (gm0 + 8 < N_NODES) {
                float2 o;
                o.x = fmaxf(acc[i][j][2] + b0, 0.f);
                o.y = fmaxf(acc[i][j][3] + b1, 0.f);
                *(float2*)(out + (size_t)(gm0 + 8) * C + col) = o;
            }
        }
    }
}

// ======================= classifier =======================
__global__ void __launch_bounds__(256)
cls_kernel(const float* __restrict__ h, const float* __restrict__ Wc,
           const float* __restrict__ bc, float* __restrict__ out) {
    __shared__ float Ws[C * NCLS];
    __shared__ float Hs[32][C];
    int t = threadIdx.x;
    for (int i = t; i < C * NCLS; i += 256) Ws[i] = Wc[i];
    int nodeBase = blockIdx.x * 32;
    for (int i = t; i < 32 * C / 4; i += 256) {
        int r = i >> 5;
        int c4 = (i & 31) * 4;
        int n = nodeBase + r;
        float4 v = make_float4(0.f, 0.f, 0.f, 0.f);
        if (n < N_NODES) v = *(const float4*)(h + n * C + c4);
        *(float4*)&Hs[r][c4] = v;
    }
    __syncthreads();
    for (int o = t; o < 32 * NCLS; o += 256) {
        int r = o / NCLS, c = o % NCLS;
        int n = nodeBase + r;
        if (n >= N_NODES) continue;
        float acc = bc[c];
#pragma unroll 8
        for (int k = 0; k < C; k++) acc += Hs[r][k] * Ws[k * NCLS + c];
        out[n * NCLS + c] = acc;
    }
}

// ======================= launch =======================
extern "C" void kernel_launch(void* const* d_in, const int* in_sizes, int n_in,
                              void* d_out, int out_size) {
    (void)in_sizes; (void)n_in; (void)out_size;
    const float* x   = (const float*)d_in[0];
    const void*  ei  = d_in[1];
    const float* Wl1 = (const float*)d_in[2];
    const float* Wr1 = (const float*)d_in[3];
    const float* b1  = (const float*)d_in[4];
    const float* Wl2 = (const float*)d_in[5];
    const float* Wr2 = (const float*)d_in[6];
    const float* b2  = (const float*)d_in[7];
    const float* Wc  = (const float*)d_in[8];
    const float* bc  = (const float*)d_in[9];
    float* out = (float*)d_out;

    int* deg_p;   cudaGetSymbolAddress((void**)&deg_p, g_deg);
    float* agg_p; cudaGetSymbolAddress((void**)&agg_p, g_agg);
    float* h1_p;  cudaGetSymbolAddress((void**)&h1_p, g_h1);
    float* h2_p;  cudaGetSymbolAddress((void**)&h2_p, g_h2);
    __nv_bfloat16 *b1hi, *b1lo, *b2hi, *b2lo;
    cudaGetSymbolAddress((void**)&b1hi, g_B1hi);
    cudaGetSymbolAddress((void**)&b1lo, g_B1lo);
    cudaGetSymbolAddress((void**)&b2hi, g_B2hi);
    cudaGetSymbolAddress((void**)&b2lo, g_B2lo);

    cudaFuncSetAttribute(sage_gemm_mma, cudaFuncAttributeMaxDynamicSharedMemorySize, SM_TOTAL);

    const int nBlocks = (N_NODES + 127) / 128;      // 391
    const int gatherBlocks = (N_NODES * 32 + 255) / 256;  // 6250
    const int edgeBlocks = (N_EDGES + 255) / 256;   // 3125

    detect_kernel<<<1, 1>>>((const unsigned int*)ei);
    prep_w_kernel<<<256, 256>>>(Wl1, Wr1, Wl2, Wr2);

    // CSR build
    zero_int_kernel<<<(N_NODES + 255) / 256, 256>>>(deg_p, N_NODES);
    deg_kernel<<<edgeBlocks, 256>>>(ei);
    scan_kernel<<<1, SCAN_T>>>();
    csrfill_kernel<<<edgeBlocks, 256>>>(ei);

    // layer 1
    gather_kernel<<<gatherBlocks, 256>>>(x, agg_p);
    sage_gemm_mma<<<nBlocks, 256, SM_TOTAL>>>(agg_p, x, b1hi, b1lo, b1, h1_p);

    // layer 2
    gather_kernel<<<gatherBlocks, 256>>>(h1_p, agg_p);
    sage_gemm_mma<<<nBlocks, 256, SM_TOTAL>>>(agg_p, h1_p, b2hi, b2lo, b2, h2_p);

    // classifier
    cls_kernel<<<(N_NODES + 31) / 32, 256>>>(h2_p, Wc, bc, out);
}

// round 6
// speedup vs baseline: 1.9381x; 1.3078x over previous
#include <cuda_runtime.h>
#include <cuda_bf16.h>
#include <cstdint>

#define N_NODES 50000
#define N_EDGES 800000
#define C 128
#define NCLS 40
#define NB_SCAN ((N_NODES + 255) / 256)   // 196

// ======================= scratch (no allocation allowed) ====================
__device__ __align__(256) float g_deg_inv[N_NODES];
__device__ __align__(256) int   g_deg[N_NODES];
__device__ __align__(256) int   g_off[N_NODES + 1];
__device__ __align__(256) int   g_cursor[N_NODES];
__device__ __align__(256) int   g_csr_src[N_EDGES];
__device__ __align__(256) int   g_bsum[NB_SCAN];
__device__ __align__(256) int   g_bpre[NB_SCAN];
// split bf16 feature images
__device__ __align__(256) __nv_bfloat16 g_agg_hi[N_NODES * C];
__device__ __align__(256) __nv_bfloat16 g_agg_lo[N_NODES * C];
__device__ __align__(256) __nv_bfloat16 g_x_hi[N_NODES * C];
__device__ __align__(256) __nv_bfloat16 g_x_lo[N_NODES * C];
__device__ __align__(256) __nv_bfloat16 g_h1_hi[N_NODES * C];
__device__ __align__(256) __nv_bfloat16 g_h1_lo[N_NODES * C];
__device__ __align__(256) float g_h1[N_NODES * C];
__device__ __align__(256) float g_h2[N_NODES * C];
// Weight images: [256 k][128 n] bf16, row-major, hi/lo split, per layer.
__device__ __align__(256) __nv_bfloat16 g_B1hi[256 * 128];
__device__ __align__(256) __nv_bfloat16 g_B1lo[256 * 128];
__device__ __align__(256) __nv_bfloat16 g_B2hi[256 * 128];
__device__ __align__(256) __nv_bfloat16 g_B2lo[256 * 128];
__device__ int g_idx64;

// ======================= helpers =======================
__device__ __forceinline__ uint32_t smem_u32(const void* p) {
    uint32_t a;
    asm("{ .reg .u64 t; cvta.to.shared.u64 t, %1; cvt.u32.u64 %0, t; }"
        : "=r"(a) : "l"(p));
    return a;
}
__device__ __forceinline__ void ldsm_x4(uint32_t& r0, uint32_t& r1,
                                        uint32_t& r2, uint32_t& r3, uint32_t addr) {
    asm volatile("ldmatrix.sync.aligned.m8n8.x4.shared.b16 {%0,%1,%2,%3}, [%4];"
                 : "=r"(r0), "=r"(r1), "=r"(r2), "=r"(r3) : "r"(addr));
}
__device__ __forceinline__ void ldsm_x4_t(uint32_t& r0, uint32_t& r1,
                                          uint32_t& r2, uint32_t& r3, uint32_t addr) {
    asm volatile("ldmatrix.sync.aligned.m8n8.x4.trans.shared.b16 {%0,%1,%2,%3}, [%4];"
                 : "=r"(r0), "=r"(r1), "=r"(r2), "=r"(r3) : "r"(addr));
}
__device__ __forceinline__ void mma_bf16(float* c, const uint32_t* a, const uint32_t* b) {
    asm volatile(
        "mma.sync.aligned.m16n8k16.row.col.f32.bf16.bf16.f32 "
        "{%0,%1,%2,%3}, {%4,%5,%6,%7}, {%8,%9}, {%0,%1,%2,%3};"
        : "+f"(c[0]), "+f"(c[1]), "+f"(c[2]), "+f"(c[3])
        : "r"(a[0]), "r"(a[1]), "r"(a[2]), "r"(a[3]), "r"(b[0]), "r"(b[1]));
}
__device__ __forceinline__ uint32_t split_pack_hi(float a, float b, uint32_t& lo) {
    __nv_bfloat16 ah = __float2bfloat16(a), bh = __float2bfloat16(b);
    __nv_bfloat16 al = __float2bfloat16(a - __bfloat162float(ah));
    __nv_bfloat16 bl = __float2bfloat16(b - __bfloat162float(bh));
    lo = ((uint32_t)__bfloat16_as_ushort(bl) << 16) | __bfloat16_as_ushort(al);
    return ((uint32_t)__bfloat16_as_ushort(bh) << 16) | __bfloat16_as_ushort(ah);
}

// ======================= small kernels =======================
__global__ void detect_kernel(const unsigned int* ei) {
    int zeros = 0;
    for (int i = 1; i < 128; i += 2) zeros += (ei[i] == 0u);
    g_idx64 = (zeros >= 32) ? 1 : 0;
}
__device__ __forceinline__ int load_edge(const void* ei, int pos, int is64) {
    return is64 ? (int)((const long long*)ei)[pos] : ((const int*)ei)[pos];
}
__global__ void zero_int_kernel(int* p, int n) {
    int i = blockIdx.x * blockDim.x + threadIdx.x;
    if (i < n) p[i] = 0;
}
__global__ void deg_kernel(const void* ei) {
    int e = blockIdx.x * blockDim.x + threadIdx.x;
    if (e >= N_EDGES) return;
    int dst = load_edge(ei, N_EDGES + e, g_idx64);
    atomicAdd(&g_deg[dst], 1);
}

// ---- 3-phase parallel scan over g_deg ----
__global__ void __launch_bounds__(256) scan_part_kernel() {
    __shared__ int sh[256];
    int t = threadIdx.x;
    int i = blockIdx.x * 256 + t;
    sh[t] = (i < N_NODES) ? g_deg[i] : 0;
    __syncthreads();
#pragma unroll
    for (int off = 128; off > 0; off >>= 1) {
        if (t < off) sh[t] += sh[t + off];
        __syncthreads();
    }
    if (t == 0) g_bsum[blockIdx.x] = sh[0];
}
__global__ void __launch_bounds__(256) scan_top_kernel() {
    __shared__ int sh[256];
    int t = threadIdx.x;
    int v = (t < NB_SCAN) ? g_bsum[t] : 0;
    sh[t] = v;
    __syncthreads();
    for (int off = 1; off < 256; off <<= 1) {
        int u = 0;
        if (t >= off) u = sh[t - off];
        __syncthreads();
        if (t >= off) sh[t] += u;
        __syncthreads();
    }
    if (t < NB_SCAN) g_bpre[t] = sh[t] - v;   // exclusive
    if (t == 0) g_off[N_NODES] = N_EDGES;
}
__global__ void __launch_bounds__(256) scan_write_kernel() {
    __shared__ int sh[256];
    int t = threadIdx.x;
    int i = blockIdx.x * 256 + t;
    int d = (i < N_NODES) ? g_deg[i] : 0;
    sh[t] = d;
    __syncthreads();
    for (int off = 1; off < 256; off <<= 1) {
        int u = 0;
        if (t >= off) u = sh[t - off];
        __syncthreads();
        if (t >= off) sh[t] += u;
        __syncthreads();
    }
    if (i < N_NODES) {
        int o = g_bpre[blockIdx.x] + sh[t] - d;
        g_off[i] = o;
        g_cursor[i] = o;
        g_deg_inv[i] = (d > 0) ? (1.0f / (float)d) : 0.0f;
    }
}

__global__ void csrfill_kernel(const void* __restrict__ ei) {
    int e = blockIdx.x * blockDim.x + threadIdx.x;
    if (e >= N_EDGES) return;
    int is64 = g_idx64;
    int src = load_edge(ei, e, is64);
    int dst = load_edge(ei, N_EDGES + e, is64);
    int pos = atomicAdd(&g_cursor[dst], 1);
    g_csr_src[pos] = src;
}

// Weight prep: B[k][n] = W[k mod 128][n] from Wl (k<128) else Wr; bf16 hi/lo split.
__global__ void prep_w_kernel(const float* __restrict__ Wl1, const float* __restrict__ Wr1,
                              const float* __restrict__ Wl2, const float* __restrict__ Wr2) {
    int idx = blockIdx.x * blockDim.x + threadIdx.x;  // 2 * 256 * 128
    if (idx >= 2 * 256 * 128) return;
    int layer = idx >> 15;
    int rem = idx & 32767;
    int k = rem >> 7;
    int n = rem & 127;
    const float* W = (layer == 0) ? ((k < 128) ? Wl1 : Wr1) : ((k < 128) ? Wl2 : Wr2);
    float v = W[(k & 127) * 128 + n];
    __nv_bfloat16 hi = __float2bfloat16(v);
    __nv_bfloat16 lo = __float2bfloat16(v - __bfloat162float(hi));
    (layer ? g_B2hi : g_B1hi)[k * 128 + n] = hi;
    (layer ? g_B2lo : g_B1lo)[k * 128 + n] = lo;
}

// Feature split: fp32 [N*C] -> bf16 hi/lo images, float4 granularity.
__global__ void __launch_bounds__(256)
prep_split_kernel(const float* __restrict__ src, __nv_bfloat16* __restrict__ dhi,
                  __nv_bfloat16* __restrict__ dlo) {
    int i = blockIdx.x * blockDim.x + threadIdx.x;   // over N*C/4
    if (i >= N_NODES * C / 4) return;
    float4 v = ((const float4*)src)[i];
    uint2 h, l;
    h.x = split_pack_hi(v.x, v.y, l.x);
    h.y = split_pack_hi(v.z, v.w, l.y);
    ((uint2*)dhi)[i] = h;
    ((uint2*)dlo)[i] = l;
}

// ======================= CSR gather-mean: one warp per node =================
// Accumulates fp32, writes split bf16 hi/lo directly.
__global__ void __launch_bounds__(256)
gather_kernel(const float* __restrict__ feat,
              __nv_bfloat16* __restrict__ agghi, __nv_bfloat16* __restrict__ agglo) {
    int node = (blockIdx.x * blockDim.x + threadIdx.x) >> 5;
    int lane = threadIdx.x & 31;
    if (node >= N_NODES) return;
    int e = g_off[node];
    const int end = g_off[node + 1];
    float4 acc = make_float4(0.f, 0.f, 0.f, 0.f);
    for (; e + 4 <= end; e += 4) {
        int i0 = __ldg(&g_csr_src[e]);
        int i1 = __ldg(&g_csr_src[e + 1]);
        int i2 = __ldg(&g_csr_src[e + 2]);
        int i3 = __ldg(&g_csr_src[e + 3]);
        float4 v0 = *(const float4*)(feat + (size_t)i0 * C + lane * 4);
        float4 v1 = *(const float4*)(feat + (size_t)i1 * C + lane * 4);
        float4 v2 = *(const float4*)(feat + (size_t)i2 * C + lane * 4);
        float4 v3 = *(const float4*)(feat + (size_t)i3 * C + lane * 4);
        acc.x += v0.x + v1.x + v2.x + v3.x;
        acc.y += v0.y + v1.y + v2.y + v3.y;
        acc.z += v0.z + v1.z + v2.z + v3.z;
        acc.w += v0.w + v1.w + v2.w + v3.w;
    }
    for (; e < end; ++e) {
        int s = __ldg(&g_csr_src[e]);
        float4 v = *(const float4*)(feat + (size_t)s * C + lane * 4);
        acc.x += v.x; acc.y += v.y; acc.z += v.z; acc.w += v.w;
    }
    float s = g_deg_inv[node];
    acc.x *= s; acc.y *= s; acc.z *= s; acc.w *= s;
    uint2 h, l;
    h.x = split_pack_hi(acc.x, acc.y, l.x);
    h.y = split_pack_hi(acc.z, acc.w, l.y);
    size_t o = (size_t)node * C + lane * 4;
    *(uint2*)(agghi + o) = h;
    *(uint2*)(agglo + o) = l;
}

// ======================= HMMA SAGE GEMM =======================
// out = relu([agg | x] @ B + bias); A operands arrive pre-split bf16.
// BM=128, BN=128, BK=64, 8 warps (2 m x 4 n), warp tile 64x32.
#define A_STRIDE 72
#define B_STRIDE 136
#define SM_AH 0
#define SM_AL (128 * A_STRIDE * 2)
#define SM_BH (2 * 128 * A_STRIDE * 2)
#define SM_BL (2 * 128 * A_STRIDE * 2 + 64 * B_STRIDE * 2)
#define SM_TOTAL (2 * 128 * A_STRIDE * 2 + 2 * 64 * B_STRIDE * 2)  // 71680 B

__global__ void __launch_bounds__(256)
sage_gemm_mma(const __nv_bfloat16* __restrict__ agghi, const __nv_bfloat16* __restrict__ agglo,
              const __nv_bfloat16* __restrict__ xhi, const __nv_bfloat16* __restrict__ xlo,
              const __nv_bfloat16* __restrict__ Bhi, const __nv_bfloat16* __restrict__ Blo,
              const float* __restrict__ bias, float* __restrict__ out,
              __nv_bfloat16* __restrict__ outhi, __nv_bfloat16* __restrict__ outlo) {
    extern __shared__ unsigned char smem[];
    const uint32_t sbase = smem_u32(smem);
    const int t = threadIdx.x;
    const int wid = t >> 5, lane = t & 31;
    const int warp_m = wid >> 2;
    const int warp_n = wid & 3;
    const int rowBase = blockIdx.x * 128;

    float acc[4][4][4];
#pragma unroll
    for (int i = 0; i < 4; i++)
#pragma unroll
        for (int j = 0; j < 4; j++)
#pragma unroll
            for (int r = 0; r < 4; r++) acc[i][j][r] = 0.f;

    const int a_row = warp_m * 64 + (lane & 15);
    const int a_col = (lane >> 4) * 8;
    const int b_row = (lane & 7) + (lane & 8);
    const int b_col = warp_n * 32 + (lane >> 4) * 8;

    for (int chunk = 0; chunk < 4; ++chunk) {
        const int k0 = chunk * 64;
        const bool isAgg = (chunk < 2);
        const __nv_bfloat16* shi = isAgg ? agghi : xhi;
        const __nv_bfloat16* slo = isAgg ? agglo : xlo;
        const int koff = isAgg ? k0 : (k0 - 128);

        // ---- fill A hi/lo: pure uint4 copies of pre-split images ----
#pragma unroll
        for (int it = 0; it < 8; ++it) {
            int idx = it * 256 + t;          // 0..2047
            int split = idx >> 10;
            int rem = idx & 1023;
            int row = rem >> 3;              // 0..127
            int q = rem & 7;                 // uint4 within 64-k row
            int gm = rowBase + row;
            const __nv_bfloat16* g = split ? slo : shi;
            uint4 v = make_uint4(0u, 0u, 0u, 0u);
            if (gm < N_NODES) v = *(const uint4*)(g + (size_t)gm * C + koff + q * 8);
            uint32_t off = (split ? SM_AL : SM_AH) + (uint32_t)(row * A_STRIDE + q * 8) * 2;
            *(uint4*)(smem + off) = v;
        }
        // ---- fill B hi/lo: 64 k-rows x 128 n, both splits (2048 uint4) ----
#pragma unroll
        for (int it = 0; it < 8; ++it) {
            int idx = it * 256 + t;
            int split = idx >> 10;
            int rem = idx & 1023;
            int r = rem >> 4;
            int c8 = (rem & 15) * 8;
            const __nv_bfloat16* g = split ? Blo : Bhi;
            uint4 v = *(const uint4*)(g + (size_t)(k0 + r) * 128 + c8);
            uint32_t off = (split ? SM_BL : SM_BH) + (uint32_t)(r * B_STRIDE + c8) * 2;
            *(uint4*)(smem + off) = v;
        }
        __syncthreads();

        // ---- compute: 4 k-steps of 16 ----
#pragma unroll
        for (int ks = 0; ks < 4; ++ks) {
            const int kk = ks * 16;
            uint32_t ah[4][4], al[4][4], bh[4][2], bl[4][2];
#pragma unroll
            for (int i = 0; i < 4; ++i) {
                uint32_t addr = sbase + SM_AH +
                    (uint32_t)((a_row + i * 16) * A_STRIDE + kk + a_col) * 2;
                ldsm_x4(ah[i][0], ah[i][1], ah[i][2], ah[i][3], addr);
                ldsm_x4(al[i][0], al[i][1], al[i][2], al[i][3], addr + (SM_AL - SM_AH));
            }
#pragma unroll
            for (int jj = 0; jj < 2; ++jj) {
                uint32_t addr = sbase + SM_BH +
                    (uint32_t)((kk + b_row) * B_STRIDE + b_col + jj * 16) * 2;
                ldsm_x4_t(bh[jj * 2][0], bh[jj * 2][1], bh[jj * 2 + 1][0], bh[jj * 2 + 1][1], addr);
                ldsm_x4_t(bl[jj * 2][0], bl[jj * 2][1], bl[jj * 2 + 1][0], bl[jj * 2 + 1][1],
                          addr + (SM_BL - SM_BH));
            }
#pragma unroll
            for (int i = 0; i < 4; ++i)
#pragma unroll
                for (int j = 0; j < 4; ++j) {
                    mma_bf16(acc[i][j], ah[i], bh[j]);
                    mma_bf16(acc[i][j], ah[i], bl[j]);
                    mma_bf16(acc[i][j], al[i], bh[j]);
                }
        }
        __syncthreads();
    }

    // ---- epilogue: bias + relu; store fp32 (+ optional bf16 split) ----
    const int er = lane >> 2;
    const int ec = (lane & 3) * 2;
#pragma unroll
    for (int i = 0; i < 4; ++i) {
        int gm0 = rowBase + warp_m * 64 + i * 16 + er;
#pragma unroll
        for (int j = 0; j < 4; ++j) {
            int col = warp_n * 32 + j * 8 + ec;
            float b0 = bias[col], b1 = bias[col + 1];
            if (gm0 < N_NODES) {
                float2 o;
                o.x = fmaxf(acc[i][j][0] + b0, 0.f);
                o.y = fmaxf(acc[i][j][1] + b1, 0.f);
                *(float2*)(out + (size_t)gm0 * C + col) = o;
                if (outhi) {
                    uint32_t lw, hw = split_pack_hi(o.x, o.y, lw);
                    *(uint32_t*)(outhi + (size_t)gm0 * C + col) = hw;
                    *(uint32_t*)(outlo + (size_t)gm0 * C + col) = lw;
                }
            }
            if (gm0 + 8 < N_NODES) {
                float2 o;
                o.x = fmaxf(acc[i][j][2] + b0, 0.f);
                o.y = fmaxf(acc[i][j][3] + b1, 0.f);
                *(float2*)(out + (size_t)(gm0 + 8) * C + col) = o;
                if (outhi) {
                    uint32_t lw, hw = split_pack_hi(o.x, o.y, lw);
                    *(uint32_t*)(outhi + (size_t)(gm0 + 8) * C + col) = hw;
                    *(uint32_t*)(outlo + (size_t)(gm0 + 8) * C + col) = lw;
                }
            }
        }
    }
}

// ======================= classifier =======================
__global__ void __launch_bounds__(256)
cls_kernel(const float* __restrict__ h, const float* __restrict__ Wc,
           const float* __restrict__ bc, float* __restrict__ out) {
    __shared__ float Ws[C * NCLS];
    __shared__ float Hs[32][C];
    int t = threadIdx.x;
    for (int i = t; i < C * NCLS; i += 256) Ws[i] = Wc[i];
    int nodeBase = blockIdx.x * 32;
    for (int i = t; i < 32 * C / 4; i += 256) {
        int r = i >> 5;
        int c4 = (i & 31) * 4;
        int n = nodeBase + r;
        float4 v = make_float4(0.f, 0.f, 0.f, 0.f);
        if (n < N_NODES) v = *(const float4*)(h + n * C + c4);
        *(float4*)&Hs[r][c4] = v;
    }
    __syncthreads();
    for (int o = t; o < 32 * NCLS; o += 256) {
        int r = o / NCLS, c = o % NCLS;
        int n = nodeBase + r;
        if (n >= N_NODES) continue;
        float acc = bc[c];
#pragma unroll 8
        for (int k = 0; k < C; k++) acc += Hs[r][k] * Ws[k * NCLS + c];
        out[n * NCLS + c] = acc;
    }
}

// ======================= launch =======================
extern "C" void kernel_launch(void* const* d_in, const int* in_sizes, int n_in,
                              void* d_out, int out_size) {
    (void)in_sizes; (void)n_in; (void)out_size;
    const float* x   = (const float*)d_in[0];
    const void*  ei  = d_in[1];
    const float* Wl1 = (const float*)d_in[2];
    const float* Wr1 = (const float*)d_in[3];
    const float* b1  = (const float*)d_in[4];
    const float* Wl2 = (const float*)d_in[5];
    const float* Wr2 = (const float*)d_in[6];
    const float* b2  = (const float*)d_in[7];
    const float* Wc  = (const float*)d_in[8];
    const float* bc  = (const float*)d_in[9];
    float* out = (float*)d_out;

    int* deg_p;   cudaGetSymbolAddress((void**)&deg_p, g_deg);
    float* h1_p;  cudaGetSymbolAddress((void**)&h1_p, g_h1);
    float* h2_p;  cudaGetSymbolAddress((void**)&h2_p, g_h2);
    __nv_bfloat16 *agghi, *agglo, *xhi, *xlo, *h1hi, *h1lo;
    cudaGetSymbolAddress((void**)&agghi, g_agg_hi);
    cudaGetSymbolAddress((void**)&agglo, g_agg_lo);
    cudaGetSymbolAddress((void**)&xhi, g_x_hi);
    cudaGetSymbolAddress((void**)&xlo, g_x_lo);
    cudaGetSymbolAddress((void**)&h1hi, g_h1_hi);
    cudaGetSymbolAddress((void**)&h1lo, g_h1_lo);
    __nv_bfloat16 *b1hi, *b1lo, *b2hi, *b2lo;
    cudaGetSymbolAddress((void**)&b1hi, g_B1hi);
    cudaGetSymbolAddress((void**)&b1lo, g_B1lo);
    cudaGetSymbolAddress((void**)&b2hi, g_B2hi);
    cudaGetSymbolAddress((void**)&b2lo, g_B2lo);

    cudaFuncSetAttribute(sage_gemm_mma, cudaFuncAttributeMaxDynamicSharedMemorySize, SM_TOTAL);

    const int nBlocks = (N_NODES + 127) / 128;            // 391
    const int gatherBlocks = (N_NODES * 32 + 255) / 256;  // 6250
    const int edgeBlocks = (N_EDGES + 255) / 256;         // 3125
    const int splitBlocks = (N_NODES * C / 4 + 255) / 256;

    detect_kernel<<<1, 1>>>((const unsigned int*)ei);
    prep_w_kernel<<<256, 256>>>(Wl1, Wr1, Wl2, Wr2);
    prep_split_kernel<<<splitBlocks, 256>>>(x, xhi, xlo);

    // CSR build
    zero_int_kernel<<<(N_NODES + 255) / 256, 256>>>(deg_p, N_NODES);
    deg_kernel<<<edgeBlocks, 256>>>(ei);
    scan_part_kernel<<<NB_SCAN, 256>>>();
    scan_top_kernel<<<1, 256>>>();
    scan_write_kernel<<<NB_SCAN, 256>>>();
    csrfill_kernel<<<edgeBlocks, 256>>>(ei);

    // layer 1
    gather_kernel<<<gatherBlocks, 256>>>(x, agghi, agglo);
    sage_gemm_mma<<<nBlocks, 256, SM_TOTAL>>>(agghi, agglo, xhi, xlo,
                                              b1hi, b1lo, b1, h1_p, h1hi, h1lo);

    // layer 2
    gather_kernel<<<gatherBlocks, 256>>>(h1_p, agghi, agglo);
    sage_gemm_mma<<<nBlocks, 256, SM_TOTAL>>>(agghi, agglo, h1hi, h1lo,
                                              b2hi, b2lo, b2, h2_p, (__nv_bfloat16*)0,
                                              (__nv_bfloat16*)0);

    // classifier
    cls_kernel<<<(N_NODES + 31) / 32, 256>>>(h2_p, Wc, bc, out);
}

// round 7
// speedup vs baseline: 2.3848x; 1.2305x over previous
#include <cuda_runtime.h>
#include <cuda_bf16.h>
#include <cstdint>

#define N_NODES 50000
#define N_EDGES 800000
#define C 128
#define NCLS 40
#define NB_SCAN ((N_NODES + 255) / 256)   // 196

// ======================= scratch (no allocation allowed) ====================
__device__ __align__(256) float g_deg_inv[N_NODES];
__device__ __align__(256) int   g_deg[N_NODES];
__device__ __align__(256) int   g_off[N_NODES + 1];
__device__ __align__(256) int   g_cursor[N_NODES];
__device__ __align__(256) int   g_csr_src[N_EDGES];
__device__ __align__(256) int   g_bsum[NB_SCAN];
__device__ __align__(256) int   g_bpre[NB_SCAN];
// split bf16 feature images (g_x_* is reused as the h2 split after GEMM1 consumes it)
__device__ __align__(256) __nv_bfloat16 g_agg_hi[N_NODES * C];
__device__ __align__(256) __nv_bfloat16 g_agg_lo[N_NODES * C];
__device__ __align__(256) __nv_bfloat16 g_x_hi[N_NODES * C];
__device__ __align__(256) __nv_bfloat16 g_x_lo[N_NODES * C];
__device__ __align__(256) __nv_bfloat16 g_h1_hi[N_NODES * C];
__device__ __align__(256) __nv_bfloat16 g_h1_lo[N_NODES * C];
__device__ __align__(256) float g_h1[N_NODES * C];
// Weight images: [256 k][128 n] bf16 row-major hi/lo per layer; Wc [128 k][64 n].
__device__ __align__(256) __nv_bfloat16 g_B1hi[256 * 128];
__device__ __align__(256) __nv_bfloat16 g_B1lo[256 * 128];
__device__ __align__(256) __nv_bfloat16 g_B2hi[256 * 128];
__device__ __align__(256) __nv_bfloat16 g_B2lo[256 * 128];
__device__ __align__(256) __nv_bfloat16 g_Wchi[128 * 64];
__device__ __align__(256) __nv_bfloat16 g_Wclo[128 * 64];
__device__ int g_idx64;

// ======================= helpers =======================
__device__ __forceinline__ uint32_t smem_u32(const void* p) {
    uint32_t a;
    asm("{ .reg .u64 t; cvta.to.shared.u64 t, %1; cvt.u32.u64 %0, t; }"
        : "=r"(a) : "l"(p));
    return a;
}
__device__ __forceinline__ void ldsm_x4(uint32_t& r0, uint32_t& r1,
                                        uint32_t& r2, uint32_t& r3, uint32_t addr) {
    asm volatile("ldmatrix.sync.aligned.m8n8.x4.shared.b16 {%0,%1,%2,%3}, [%4];"
                 : "=r"(r0), "=r"(r1), "=r"(r2), "=r"(r3) : "r"(addr));
}
__device__ __forceinline__ void ldsm_x4_t(uint32_t& r0, uint32_t& r1,
                                          uint32_t& r2, uint32_t& r3, uint32_t addr) {
    asm volatile("ldmatrix.sync.aligned.m8n8.x4.trans.shared.b16 {%0,%1,%2,%3}, [%4];"
                 : "=r"(r0), "=r"(r1), "=r"(r2), "=r"(r3) : "r"(addr));
}
__device__ __forceinline__ void mma_bf16(float* c, const uint32_t* a, const uint32_t* b) {
    asm volatile(
        "mma.sync.aligned.m16n8k16.row.col.f32.bf16.bf16.f32 "
        "{%0,%1,%2,%3}, {%4,%5,%6,%7}, {%8,%9}, {%0,%1,%2,%3};"
        : "+f"(c[0]), "+f"(c[1]), "+f"(c[2]), "+f"(c[3])
        : "r"(a[0]), "r"(a[1]), "r"(a[2]), "r"(a[3]), "r"(b[0]), "r"(b[1]));
}
__device__ __forceinline__ uint32_t split_pack_hi(float a, float b, uint32_t& lo) {
    __nv_bfloat16 ah = __float2bfloat16(a), bh = __float2bfloat16(b);
    __nv_bfloat16 al = __float2bfloat16(a - __bfloat162float(ah));
    __nv_bfloat16 bl = __float2bfloat16(b - __bfloat162float(bh));
    lo = ((uint32_t)__bfloat16_as_ushort(bl) << 16) | __bfloat16_as_ushort(al);
    return ((uint32_t)__bfloat16_as_ushort(bh) << 16) | __bfloat16_as_ushort(ah);
}
__device__ __forceinline__ int load_edge(const void* ei, int pos, int is64) {
    return is64 ? (int)((const long long*)ei)[pos] : ((const int*)ei)[pos];
}

// ======================= init: detect idx width + zero degree ================
__global__ void init_kernel(const unsigned int* ei) {
    int i = blockIdx.x * blockDim.x + threadIdx.x;
    if (i < N_NODES) g_deg[i] = 0;
    if (i == 0) {
        int zeros = 0;
        for (int j = 1; j < 128; j += 2) zeros += (ei[j] == 0u);
        g_idx64 = (zeros >= 32) ? 1 : 0;
    }
}

// degree histogram, 2 edges/thread
__global__ void deg_kernel(const void* ei) {
    int i = blockIdx.x * blockDim.x + threadIdx.x;
    int e = i * 2;
    if (e >= N_EDGES) return;
    int d0, d1;
    if (g_idx64) {
        longlong2 v = ((const longlong2*)((const long long*)ei + N_EDGES))[i];
        d0 = (int)v.x; d1 = (int)v.y;
    } else {
        int2 v = ((const int2*)((const int*)ei + N_EDGES))[i];
        d0 = v.x; d1 = v.y;
    }
    atomicAdd(&g_deg[d0], 1);
    atomicAdd(&g_deg[d1], 1);
}

// ---- 3-phase parallel scan over g_deg ----
__global__ void __launch_bounds__(256) scan_part_kernel() {
    __shared__ int sh[256];
    int t = threadIdx.x;
    int i = blockIdx.x * 256 + t;
    sh[t] = (i < N_NODES) ? g_deg[i] : 0;
    __syncthreads();
#pragma unroll
    for (int off = 128; off > 0; off >>= 1) {
        if (t < off) sh[t] += sh[t + off];
        __syncthreads();
    }
    if (t == 0) g_bsum[blockIdx.x] = sh[0];
}
__global__ void __launch_bounds__(256) scan_top_kernel() {
    __shared__ int sh[256];
    int t = threadIdx.x;
    int v = (t < NB_SCAN) ? g_bsum[t] : 0;
    sh[t] = v;
    __syncthreads();
    for (int off = 1; off < 256; off <<= 1) {
        int u = 0;
        if (t >= off) u = sh[t - off];
        __syncthreads();
        if (t >= off) sh[t] += u;
        __syncthreads();
    }
    if (t < NB_SCAN) g_bpre[t] = sh[t] - v;
    if (t == 0) g_off[N_NODES] = N_EDGES;
}
__global__ void __launch_bounds__(256) scan_write_kernel() {
    __shared__ int sh[256];
    int t = threadIdx.x;
    int i = blockIdx.x * 256 + t;
    int d = (i < N_NODES) ? g_deg[i] : 0;
    sh[t] = d;
    __syncthreads();
    for (int off = 1; off < 256; off <<= 1) {
        int u = 0;
        if (t >= off) u = sh[t - off];
        __syncthreads();
        if (t >= off) sh[t] += u;
        __syncthreads();
    }
    if (i < N_NODES) {
        int o = g_bpre[blockIdx.x] + sh[t] - d;
        g_off[i] = o;
        g_cursor[i] = o;
        g_deg_inv[i] = (d > 0) ? (1.0f / (float)d) : 0.0f;
    }
}

// CSR fill, 2 edges/thread
__global__ void csrfill_kernel(const void* __restrict__ ei) {
    int i = blockIdx.x * blockDim.x + threadIdx.x;
    int e = i * 2;
    if (e >= N_EDGES) return;
    int s0, s1, d0, d1;
    if (g_idx64) {
        longlong2 sv = ((const longlong2*)(const long long*)ei)[i];
        longlong2 dv = ((const longlong2*)((const long long*)ei + N_EDGES))[i];
        s0 = (int)sv.x; s1 = (int)sv.y; d0 = (int)dv.x; d1 = (int)dv.y;
    } else {
        int2 sv = ((const int2*)(const int*)ei)[i];
        int2 dv = ((const int2*)((const int*)ei + N_EDGES))[i];
        s0 = sv.x; s1 = sv.y; d0 = dv.x; d1 = dv.y;
    }
    g_csr_src[atomicAdd(&g_cursor[d0], 1)] = s0;
    g_csr_src[atomicAdd(&g_cursor[d1], 1)] = s1;
}

// Weight prep: layers 1,2 [256k x 128n] + classifier [128k x 64n padded].
__global__ void prep_w_kernel(const float* __restrict__ Wl1, const float* __restrict__ Wr1,
                              const float* __restrict__ Wl2, const float* __restrict__ Wr2,
                              const float* __restrict__ Wc) {
    int idx = blockIdx.x * blockDim.x + threadIdx.x;
    if (idx < 2 * 256 * 128) {
        int layer = idx >> 15;
        int rem = idx & 32767;
        int k = rem >> 7;
        int n = rem & 127;
        const float* W = (layer == 0) ? ((k < 128) ? Wl1 : Wr1) : ((k < 128) ? Wl2 : Wr2);
        float v = W[(k & 127) * 128 + n];
        __nv_bfloat16 hi = __float2bfloat16(v);
        __nv_bfloat16 lo = __float2bfloat16(v - __bfloat162float(hi));
        (layer ? g_B2hi : g_B1hi)[k * 128 + n] = hi;
        (layer ? g_B2lo : g_B1lo)[k * 128 + n] = lo;
    } else if (idx < 2 * 256 * 128 + 128 * 64) {
        int rem = idx - 2 * 256 * 128;
        int k = rem >> 6;
        int n = rem & 63;
        float v = (n < NCLS) ? Wc[k * NCLS + n] : 0.f;
        __nv_bfloat16 hi = __float2bfloat16(v);
        __nv_bfloat16 lo = __float2bfloat16(v - __bfloat162float(hi));
        g_Wchi[k * 64 + n] = hi;
        g_Wclo[k * 64 + n] = lo;
    }
}

// Feature split: fp32 [N*C] -> bf16 hi/lo images.
__global__ void __launch_bounds__(256)
prep_split_kernel(const float* __restrict__ src, __nv_bfloat16* __restrict__ dhi,
                  __nv_bfloat16* __restrict__ dlo) {
    int i = blockIdx.x * blockDim.x + threadIdx.x;
    if (i >= N_NODES * C / 4) return;
    float4 v = ((const float4*)src)[i];
    uint2 h, l;
    h.x = split_pack_hi(v.x, v.y, l.x);
    h.y = split_pack_hi(v.z, v.w, l.y);
    ((uint2*)dhi)[i] = h;
    ((uint2*)dlo)[i] = l;
}

// ======================= CSR gather-mean: one warp per node =================
__global__ void __launch_bounds__(256)
gather_kernel(const float* __restrict__ feat,
              __nv_bfloat16* __restrict__ agghi, __nv_bfloat16* __restrict__ agglo) {
    int node = (blockIdx.x * blockDim.x + threadIdx.x) >> 5;
    int lane = threadIdx.x & 31;
    if (node >= N_NODES) return;
    int e = g_off[node];
    const int end = g_off[node + 1];
    float4 acc = make_float4(0.f, 0.f, 0.f, 0.f);
    for (; e + 4 <= end; e += 4) {
        int i0 = __ldg(&g_csr_src[e]);
        int i1 = __ldg(&g_csr_src[e + 1]);
        int i2 = __ldg(&g_csr_src[e + 2]);
        int i3 = __ldg(&g_csr_src[e + 3]);
        float4 v0 = *(const float4*)(feat + (size_t)i0 * C + lane * 4);
        float4 v1 = *(const float4*)(feat + (size_t)i1 * C + lane * 4);
        float4 v2 = *(const float4*)(feat + (size_t)i2 * C + lane * 4);
        float4 v3 = *(const float4*)(feat + (size_t)i3 * C + lane * 4);
        acc.x += v0.x + v1.x + v2.x + v3.x;
        acc.y += v0.y + v1.y + v2.y + v3.y;
        acc.z += v0.z + v1.z + v2.z + v3.z;
        acc.w += v0.w + v1.w + v2.w + v3.w;
    }
    for (; e < end; ++e) {
        int s = __ldg(&g_csr_src[e]);
        float4 v = *(const float4*)(feat + (size_t)s * C + lane * 4);
        acc.x += v.x; acc.y += v.y; acc.z += v.z; acc.w += v.w;
    }
    float s = g_deg_inv[node];
    acc.x *= s; acc.y *= s; acc.z *= s; acc.w *= s;
    uint2 h, l;
    h.x = split_pack_hi(acc.x, acc.y, l.x);
    h.y = split_pack_hi(acc.z, acc.w, l.y);
    size_t o = (size_t)node * C + lane * 4;
    *(uint2*)(agghi + o) = h;
    *(uint2*)(agglo + o) = l;
}

// ======================= HMMA SAGE GEMM =======================
#define A_STRIDE 72
#define B_STRIDE 136
#define SM_AH 0
#define SM_AL (128 * A_STRIDE * 2)
#define SM_BH (2 * 128 * A_STRIDE * 2)
#define SM_BL (2 * 128 * A_STRIDE * 2 + 64 * B_STRIDE * 2)
#define SM_TOTAL (2 * 128 * A_STRIDE * 2 + 2 * 64 * B_STRIDE * 2)  // 71680 B

__global__ void __launch_bounds__(256)
sage_gemm_mma(const __nv_bfloat16* __restrict__ agghi, const __nv_bfloat16* __restrict__ agglo,
              const __nv_bfloat16* __restrict__ xhi, const __nv_bfloat16* __restrict__ xlo,
              const __nv_bfloat16* __restrict__ Bhi, const __nv_bfloat16* __restrict__ Blo,
              const float* __restrict__ bias, float* __restrict__ out,
              __nv_bfloat16* __restrict__ outhi, __nv_bfloat16* __restrict__ outlo) {
    extern __shared__ unsigned char smem[];
    const uint32_t sbase = smem_u32(smem);
    const int t = threadIdx.x;
    const int wid = t >> 5, lane = t & 31;
    const int warp_m = wid >> 2;
    const int warp_n = wid & 3;
    const int rowBase = blockIdx.x * 128;

    float acc[4][4][4];
#pragma unroll
    for (int i = 0; i < 4; i++)
#pragma unroll
        for (int j = 0; j < 4; j++)
#pragma unroll
            for (int r = 0; r < 4; r++) acc[i][j][r] = 0.f;

    const int a_row = warp_m * 64 + (lane & 15);
    const int a_col = (lane >> 4) * 8;
    const int b_row = (lane & 7) + (lane & 8);
    const int b_col = warp_n * 32 + (lane >> 4) * 8;

    for (int chunk = 0; chunk < 4; ++chunk) {
        const int k0 = chunk * 64;
        const bool isAgg = (chunk < 2);
        const __nv_bfloat16* shi = isAgg ? agghi : xhi;
        const __nv_bfloat16* slo = isAgg ? agglo : xlo;
        const int koff = isAgg ? k0 : (k0 - 128);

#pragma unroll
        for (int it = 0; it < 8; ++it) {
            int idx = it * 256 + t;
            int split = idx >> 10;
            int rem = idx & 1023;
            int row = rem >> 3;
            int q = rem & 7;
            int gm = rowBase + row;
            const __nv_bfloat16* g = split ? slo : shi;
            uint4 v = make_uint4(0u, 0u, 0u, 0u);
            if (gm < N_NODES) v = *(const uint4*)(g + (size_t)gm * C + koff + q * 8);
            uint32_t off = (split ? SM_AL : SM_AH) + (uint32_t)(row * A_STRIDE + q * 8) * 2;
            *(uint4*)(smem + off) = v;
        }
#pragma unroll
        for (int it = 0; it < 8; ++it) {
            int idx = it * 256 + t;
            int split = idx >> 10;
            int rem = idx & 1023;
            int r = rem >> 4;
            int c8 = (rem & 15) * 8;
            const __nv_bfloat16* g = split ? Blo : Bhi;
            uint4 v = *(const uint4*)(g + (size_t)(k0 + r) * 128 + c8);
            uint32_t off = (split ? SM_BL : SM_BH) + (uint32_t)(r * B_STRIDE + c8) * 2;
            *(uint4*)(smem + off) = v;
        }
        __syncthreads();

#pragma unroll
        for (int ks = 0; ks < 4; ++ks) {
            const int kk = ks * 16;
            uint32_t ah[4][4], al[4][4], bh[4][2], bl[4][2];
#pragma unroll
            for (int i = 0; i < 4; ++i) {
                uint32_t addr = sbase + SM_AH +
                    (uint32_t)((a_row + i * 16) * A_STRIDE + kk + a_col) * 2;
                ldsm_x4(ah[i][0], ah[i][1], ah[i][2], ah[i][3], addr);
                ldsm_x4(al[i][0], al[i][1], al[i][2], al[i][3], addr + (SM_AL - SM_AH));
            }
#pragma unroll
            for (int jj = 0; jj < 2; ++jj) {
                uint32_t addr = sbase + SM_BH +
                    (uint32_t)((kk + b_row) * B_STRIDE + b_col + jj * 16) * 2;
                ldsm_x4_t(bh[jj * 2][0], bh[jj * 2][1], bh[jj * 2 + 1][0], bh[jj * 2 + 1][1], addr);
                ldsm_x4_t(bl[jj * 2][0], bl[jj * 2][1], bl[jj * 2 + 1][0], bl[jj * 2 + 1][1],
                          addr + (SM_BL - SM_BH));
            }
#pragma unroll
            for (int i = 0; i < 4; ++i)
#pragma unroll
                for (int j = 0; j < 4; ++j) {
                    mma_bf16(acc[i][j], ah[i], bh[j]);
                    mma_bf16(acc[i][j], ah[i], bl[j]);
                    mma_bf16(acc[i][j], al[i], bh[j]);
                }
        }
        __syncthreads();
    }

    const int er = lane >> 2;
    const int ec = (lane & 3) * 2;
#pragma unroll
    for (int i = 0; i < 4; ++i) {
        int gm0 = rowBase + warp_m * 64 + i * 16 + er;
#pragma unroll
        for (int j = 0; j < 4; ++j) {
            int col = warp_n * 32 + j * 8 + ec;
            float b0 = bias[col], b1 = bias[col + 1];
#pragma unroll
            for (int half = 0; half < 2; ++half) {
                int gm = gm0 + half * 8;
                if (gm < N_NODES) {
                    float2 o;
                    o.x = fmaxf(acc[i][j][half * 2 + 0] + b0, 0.f);
                    o.y = fmaxf(acc[i][j][half * 2 + 1] + b1, 0.f);
                    if (out) *(float2*)(out + (size_t)gm * C + col) = o;
                    if (outhi) {
                        uint32_t lw, hw = split_pack_hi(o.x, o.y, lw);
                        *(uint32_t*)(outhi + (size_t)gm * C + col) = hw;
                        *(uint32_t*)(outlo + (size_t)gm * C + col) = lw;
                    }
                }
            }
        }
    }
}

// ======================= HMMA classifier =======================
// out[m, 0..39] = h2[m,:] @ Wc + bc.  M=128/CTA, N=64 (40 used), K=128.
#define CB_STRIDE 72
#define CSM_AH 0
#define CSM_AL (128 * A_STRIDE * 2)
#define CSM_BH (2 * 128 * A_STRIDE * 2)
#define CSM_BL (2 * 128 * A_STRIDE * 2 + 64 * CB_STRIDE * 2)
#define CSM_TOTAL (2 * 128 * A_STRIDE * 2 + 2 * 64 * CB_STRIDE * 2)  // 55296 B

__global__ void __launch_bounds__(256)
cls_mma(const __nv_bfloat16* __restrict__ hhi, const __nv_bfloat16* __restrict__ hlo,
        const float* __restrict__ bc, float* __restrict__ out) {
    extern __shared__ unsigned char smem[];
    const uint32_t sbase = smem_u32(smem);
    const int t = threadIdx.x;
    const int wid = t >> 5, lane = t & 31;
    const int warp_m = wid >> 2;        // 0..1
    const int warp_n = wid & 3;         // 0..3 -> 16 cols each
    const int rowBase = blockIdx.x * 128;

    float acc[4][2][4];
#pragma unroll
    for (int i = 0; i < 4; i++)
#pragma unroll
        for (int j = 0; j < 2; j++)
#pragma unroll
            for (int r = 0; r < 4; r++) acc[i][j][r] = 0.f;

    const int a_row = warp_m * 64 + (lane & 15);
    const int a_col = (lane >> 4) * 8;
    const int b_row = (lane & 7) + (lane & 8);
    const int b_col = warp_n * 16 + (lane >> 4) * 8;

    for (int chunk = 0; chunk < 2; ++chunk) {
        const int k0 = chunk * 64;
        // A fill: 128 rows x 64 k, hi+lo (2048 uint4)
#pragma unroll
        for (int it = 0; it < 8; ++it) {
            int idx = it * 256 + t;
            int split = idx >> 10;
            int rem = idx & 1023;
            int row = rem >> 3;
            int q = rem & 7;
            int gm = rowBase + row;
            const __nv_bfloat16* g = split ? hlo : hhi;
            uint4 v = make_uint4(0u, 0u, 0u, 0u);
            if (gm < N_NODES) v = *(const uint4*)(g + (size_t)gm * C + k0 + q * 8);
            uint32_t off = (split ? CSM_AL : CSM_AH) + (uint32_t)(row * A_STRIDE + q * 8) * 2;
            *(uint4*)(smem + off) = v;
        }
        // B fill: 64 k-rows x 64 n, hi+lo (1024 uint4)
#pragma unroll
        for (int it = 0; it < 4; ++it) {
            int idx = it * 256 + t;
            int split = idx >> 9;
            int rem = idx & 511;
            int r = rem >> 3;
            int c8 = (rem & 7) * 8;
            const __nv_bfloat16* g = split ? g_Wclo : g_Wchi;
            uint4 v = *(const uint4*)(g + (size_t)(k0 + r) * 64 + c8);
            uint32_t off = (split ? CSM_BL : CSM_BH) + (uint32_t)(r * CB_STRIDE + c8) * 2;
            *(uint4*)(smem + off) = v;
        }
        __syncthreads();

#pragma unroll
        for (int ks = 0; ks < 4; ++ks) {
            const int kk = ks * 16;
            uint32_t ah[4][4], al[4][4], bh[2][2], bl[2][2];
#pragma unroll
            for (int i = 0; i < 4; ++i) {
                uint32_t addr = sbase + CSM_AH +
                    (uint32_t)((a_row + i * 16) * A_STRIDE + kk + a_col) * 2;
                ldsm_x4(ah[i][0], ah[i][1], ah[i][2], ah[i][3], addr);
                ldsm_x4(al[i][0], al[i][1], al[i][2], al[i][3], addr + (CSM_AL - CSM_AH));
            }
            {
                uint32_t addr = sbase + CSM_BH +
                    (uint32_t)((kk + b_row) * CB_STRIDE + b_col) * 2;
                ldsm_x4_t(bh[0][0], bh[0][1], bh[1][0], bh[1][1], addr);
                ldsm_x4_t(bl[0][0], bl[0][1], bl[1][0], bl[1][1], addr + (CSM_BL - CSM_BH));
            }
#pragma unroll
            for (int i = 0; i < 4; ++i)
#pragma unroll
                for (int j = 0; j < 2; ++j) {
                    mma_bf16(acc[i][j], ah[i], bh[j]);
                    mma_bf16(acc[i][j], ah[i], bl[j]);
                    mma_bf16(acc[i][j], al[i], bh[j]);
                }
        }
        __syncthreads();
    }

    const int er = lane >> 2;
    const int ec = (lane & 3) * 2;
#pragma unroll
    for (int i = 0; i < 4; ++i) {
        int gm0 = rowBase + warp_m * 64 + i * 16 + er;
#pragma unroll
        for (int j = 0; j < 2; ++j) {
            int col = warp_n * 16 + j * 8 + ec;
            if (col >= NCLS) continue;
            float b0 = bc[col], b1 = bc[col + 1];
#pragma unroll
            for (int half = 0; half < 2; ++half) {
                int gm = gm0 + half * 8;
                if (gm < N_NODES) {
                    float2 o;
                    o.x = acc[i][j][half * 2 + 0] + b0;
                    o.y = acc[i][j][half * 2 + 1] + b1;
                    *(float2*)(out + (size_t)gm * NCLS + col) = o;
                }
            }
        }
    }
}

// ======================= launch =======================
extern "C" void kernel_launch(void* const* d_in, const int* in_sizes, int n_in,
                              void* d_out, int out_size) {
    (void)in_sizes; (void)n_in; (void)out_size;
    const float* x   = (const float*)d_in[0];
    const void*  ei  = d_in[1];
    const float* Wl1 = (const float*)d_in[2];
    const float* Wr1 = (const float*)d_in[3];
    const float* b1  = (const float*)d_in[4];
    const float* Wl2 = (const float*)d_in[5];
    const float* Wr2 = (const float*)d_in[6];
    const float* b2  = (const float*)d_in[7];
    const float* Wc  = (const float*)d_in[8];
    const float* bc  = (const float*)d_in[9];
    float* out = (float*)d_out;

    float* h1_p;  cudaGetSymbolAddress((void**)&h1_p, g_h1);
    __nv_bfloat16 *agghi, *agglo, *xhi, *xlo, *h1hi, *h1lo;
    cudaGetSymbolAddress((void**)&agghi, g_agg_hi);
    cudaGetSymbolAddress((void**)&agglo, g_agg_lo);
    cudaGetSymbolAddress((void**)&xhi, g_x_hi);
    cudaGetSymbolAddress((void**)&xlo, g_x_lo);
    cudaGetSymbolAddress((void**)&h1hi, g_h1_hi);
    cudaGetSymbolAddress((void**)&h1lo, g_h1_lo);
    __nv_bfloat16 *b1hi, *b1lo, *b2hi, *b2lo;
    cudaGetSymbolAddress((void**)&b1hi, g_B1hi);
    cudaGetSymbolAddress((void**)&b1lo, g_B1lo);
    cudaGetSymbolAddress((void**)&b2hi, g_B2hi);
    cudaGetSymbolAddress((void**)&b2lo, g_B2lo);

    cudaFuncSetAttribute(sage_gemm_mma, cudaFuncAttributeMaxDynamicSharedMemorySize, SM_TOTAL);
    cudaFuncSetAttribute(cls_mma, cudaFuncAttributeMaxDynamicSharedMemorySize, CSM_TOTAL);

    const int nBlocks = (N_NODES + 127) / 128;            // 391
    const int gatherBlocks = (N_NODES * 32 + 255) / 256;  // 6250
    const int edge2Blocks = (N_EDGES / 2 + 255) / 256;    // 1563
    const int splitBlocks = (N_NODES * C / 4 + 255) / 256;
    const int prepWThreads = 2 * 256 * 128 + 128 * 64;

    init_kernel<<<NB_SCAN, 256>>>((const unsigned int*)ei);
    prep_w_kernel<<<(prepWThreads + 255) / 256, 256>>>(Wl1, Wr1, Wl2, Wr2, Wc);
    prep_split_kernel<<<splitBlocks, 256>>>(x, xhi, xlo);

    // CSR build
    deg_kernel<<<edge2Blocks, 256>>>(ei);
    scan_part_kernel<<<NB_SCAN, 256>>>();
    scan_top_kernel<<<1, 256>>>();
    scan_write_kernel<<<NB_SCAN, 256>>>();
    csrfill_kernel<<<edge2Blocks, 256>>>(ei);

    // layer 1
    gather_kernel<<<gatherBlocks, 256>>>(x, agghi, agglo);
    sage_gemm_mma<<<nBlocks, 256, SM_TOTAL>>>(agghi, agglo, xhi, xlo,
                                              b1hi, b1lo, b1, h1_p, h1hi, h1lo);

    // layer 2 (h2 emitted as bf16 splits only, into the retired x-split buffers)
    gather_kernel<<<gatherBlocks, 256>>>(h1_p, agghi, agglo);
    sage_gemm_mma<<<nBlocks, 256, SM_TOTAL>>>(agghi, agglo, h1hi, h1lo,
                                              b2hi, b2lo, b2, (float*)0, xhi, xlo);

    // classifier (tensor cores)
    cls_mma<<<nBlocks, 256, CSM_TOTAL>>>(xhi, xlo, bc, out);
}

// round 8
// speedup vs baseline: 2.5894x; 1.0858x over previous
#include <cuda_runtime.h>
#include <cuda_bf16.h>
#include <cuda_fp16.h>
#include <cstdint>

#define N_NODES 50000
#define N_EDGES 800000
#define C 128
#define NCLS 40
#define NB_SCAN ((N_NODES + 255) / 256)   // 196

// ======================= scratch (no allocation allowed) ====================
__device__ __align__(256) float g_deg_inv[N_NODES];
__device__ __align__(256) int   g_deg[N_NODES];
__device__ __align__(256) int   g_off[N_NODES + 1];
__device__ __align__(256) int   g_cursor[N_NODES];
__device__ __align__(256) int   g_csr_src[N_EDGES];
__device__ __align__(256) int   g_bsum[NB_SCAN];
// split bf16 feature images (g_x_* reused as the h2 split after GEMM1 consumes it)
__device__ __align__(256) __nv_bfloat16 g_agg_hi[N_NODES * C];
__device__ __align__(256) __nv_bfloat16 g_agg_lo[N_NODES * C];
__device__ __align__(256) __nv_bfloat16 g_x_hi[N_NODES * C];
__device__ __align__(256) __nv_bfloat16 g_x_lo[N_NODES * C];
__device__ __align__(256) __nv_bfloat16 g_h1_hi[N_NODES * C];
__device__ __align__(256) __nv_bfloat16 g_h1_lo[N_NODES * C];
// fp16 gather-source images
__device__ __align__(256) __half g_x_f16[N_NODES * C];
__device__ __align__(256) __half g_h1_f16[N_NODES * C];
// Weight images
__device__ __align__(256) __nv_bfloat16 g_B1hi[256 * 128];
__device__ __align__(256) __nv_bfloat16 g_B1lo[256 * 128];
__device__ __align__(256) __nv_bfloat16 g_B2hi[256 * 128];
__device__ __align__(256) __nv_bfloat16 g_B2lo[256 * 128];
__device__ __align__(256) __nv_bfloat16 g_Wchi[128 * 64];
__device__ __align__(256) __nv_bfloat16 g_Wclo[128 * 64];
__device__ int g_idx64;

// ======================= helpers =======================
__device__ __forceinline__ uint32_t smem_u32(const void* p) {
    uint32_t a;
    asm("{ .reg .u64 t; cvta.to.shared.u64 t, %1; cvt.u32.u64 %0, t; }"
        : "=r"(a) : "l"(p));
    return a;
}
__device__ __forceinline__ void ldsm_x4(uint32_t& r0, uint32_t& r1,
                                        uint32_t& r2, uint32_t& r3, uint32_t addr) {
    asm volatile("ldmatrix.sync.aligned.m8n8.x4.shared.b16 {%0,%1,%2,%3}, [%4];"
                 : "=r"(r0), "=r"(r1), "=r"(r2), "=r"(r3) : "r"(addr));
}
__device__ __forceinline__ void ldsm_x4_t(uint32_t& r0, uint32_t& r1,
                                          uint32_t& r2, uint32_t& r3, uint32_t addr) {
    asm volatile("ldmatrix.sync.aligned.m8n8.x4.trans.shared.b16 {%0,%1,%2,%3}, [%4];"
                 : "=r"(r0), "=r"(r1), "=r"(r2), "=r"(r3) : "r"(addr));
}
__device__ __forceinline__ void mma_bf16(float* c, const uint32_t* a, const uint32_t* b) {
    asm volatile(
        "mma.sync.aligned.m16n8k16.row.col.f32.bf16.bf16.f32 "
        "{%0,%1,%2,%3}, {%4,%5,%6,%7}, {%8,%9}, {%0,%1,%2,%3};"
        : "+f"(c[0]), "+f"(c[1]), "+f"(c[2]), "+f"(c[3])
        : "r"(a[0]), "r"(a[1]), "r"(a[2]), "r"(a[3]), "r"(b[0]), "r"(b[1]));
}
__device__ __forceinline__ uint32_t split_pack_hi(float a, float b, uint32_t& lo) {
    __nv_bfloat16 ah = __float2bfloat16(a), bh = __float2bfloat16(b);
    __nv_bfloat16 al = __float2bfloat16(a - __bfloat162float(ah));
    __nv_bfloat16 bl = __float2bfloat16(b - __bfloat162float(bh));
    lo = ((uint32_t)__bfloat16_as_ushort(bl) << 16) | __bfloat16_as_ushort(al);
    return ((uint32_t)__bfloat16_as_ushort(bh) << 16) | __bfloat16_as_ushort(ah);
}

// ======================= fused prep: detect + deg-zero + weights + x-split ==
__global__ void __launch_bounds__(256)
prep_all(const unsigned int* __restrict__ ei,
         const float* __restrict__ x,
         const float* __restrict__ Wl1, const float* __restrict__ Wr1,
         const float* __restrict__ Wl2, const float* __restrict__ Wr2,
         const float* __restrict__ Wc) {
    int i = blockIdx.x * blockDim.x + threadIdx.x;
    if (i == 0) {
        int zeros = 0;
        for (int j = 1; j < 128; j += 2) zeros += (ei[j] == 0u);
        g_idx64 = (zeros >= 32) ? 1 : 0;
    }
    if (i < N_NODES) g_deg[i] = 0;
    if (i < 2 * 256 * 128) {
        int layer = i >> 15;
        int rem = i & 32767;
        int k = rem >> 7;
        int n = rem & 127;
        const float* W = (layer == 0) ? ((k < 128) ? Wl1 : Wr1) : ((k < 128) ? Wl2 : Wr2);
        float v = W[(k & 127) * 128 + n];
        __nv_bfloat16 hi = __float2bfloat16(v);
        __nv_bfloat16 lo = __float2bfloat16(v - __bfloat162float(hi));
        (layer ? g_B2hi : g_B1hi)[k * 128 + n] = hi;
        (layer ? g_B2lo : g_B1lo)[k * 128 + n] = lo;
    } else if (i < 2 * 256 * 128 + 128 * 64) {
        int rem = i - 2 * 256 * 128;
        int k = rem >> 6;
        int n = rem & 63;
        float v = (n < NCLS) ? Wc[k * NCLS + n] : 0.f;
        __nv_bfloat16 hi = __float2bfloat16(v);
        __nv_bfloat16 lo = __float2bfloat16(v - __bfloat162float(hi));
        g_Wchi[k * 64 + n] = hi;
        g_Wclo[k * 64 + n] = lo;
    }
    if (i < N_NODES * C / 4) {
        float4 v = ((const float4*)x)[i];
        uint2 h, l;
        h.x = split_pack_hi(v.x, v.y, l.x);
        h.y = split_pack_hi(v.z, v.w, l.y);
        ((uint2*)g_x_hi)[i] = h;
        ((uint2*)g_x_lo)[i] = l;
        uint2 f;
        __half2 f0 = __floats2half2_rn(v.x, v.y);
        __half2 f1 = __floats2half2_rn(v.z, v.w);
        f.x = *(uint32_t*)&f0;
        f.y = *(uint32_t*)&f1;
        ((uint2*)g_x_f16)[i] = f;
    }
}

// ======================= degree histogram, 4 edges/thread ====================
__global__ void deg_kernel(const void* ei) {
    int i = blockIdx.x * blockDim.x + threadIdx.x;
    if (i * 4 >= N_EDGES) return;
    int d0, d1, d2, d3;
    if (g_idx64) {
        const longlong2* p = (const longlong2*)((const long long*)ei + N_EDGES);
        longlong2 v0 = p[2 * i], v1 = p[2 * i + 1];
        d0 = (int)v0.x; d1 = (int)v0.y; d2 = (int)v1.x; d3 = (int)v1.y;
    } else {
        int4 v = ((const int4*)((const int*)ei + N_EDGES))[i];
        d0 = v.x; d1 = v.y; d2 = v.z; d3 = v.w;
    }
    atomicAdd(&g_deg[d0], 1);
    atomicAdd(&g_deg[d1], 1);
    atomicAdd(&g_deg[d2], 1);
    atomicAdd(&g_deg[d3], 1);
}

// ---- 2-phase parallel scan ----
__global__ void __launch_bounds__(256) scan_part_kernel() {
    __shared__ int sh[256];
    int t = threadIdx.x;
    int i = blockIdx.x * 256 + t;
    sh[t] = (i < N_NODES) ? g_deg[i] : 0;
    __syncthreads();
#pragma unroll
    for (int off = 128; off > 0; off >>= 1) {
        if (t < off) sh[t] += sh[t + off];
        __syncthreads();
    }
    if (t == 0) g_bsum[blockIdx.x] = sh[0];
}
// each block scans the 196 block sums itself, then writes its slice
__global__ void __launch_bounds__(256) scan_finish_kernel() {
    __shared__ int top[256];
    __shared__ int sh[256];
    int t = threadIdx.x;
    top[t] = (t < NB_SCAN) ? g_bsum[t] : 0;
    __syncthreads();
    for (int off = 1; off < 256; off <<= 1) {
        int u = 0;
        if (t >= off) u = top[t - off];
        __syncthreads();
        if (t >= off) top[t] += u;
        __syncthreads();
    }
    int blockPre = (blockIdx.x == 0) ? 0 : top[blockIdx.x - 1];
    int i = blockIdx.x * 256 + t;
    int d = (i < N_NODES) ? g_deg[i] : 0;
    sh[t] = d;
    __syncthreads();
    for (int off = 1; off < 256; off <<= 1) {
        int u = 0;
        if (t >= off) u = sh[t - off];
        __syncthreads();
        if (t >= off) sh[t] += u;
        __syncthreads();
    }
    if (i < N_NODES) {
        int o = blockPre + sh[t] - d;
        g_off[i] = o;
        g_cursor[i] = o;
        g_deg_inv[i] = (d > 0) ? (1.0f / (float)d) : 0.0f;
    }
    if (blockIdx.x == 0 && t == 0) g_off[N_NODES] = N_EDGES;
}

// CSR fill, 4 edges/thread
__global__ void csrfill_kernel(const void* __restrict__ ei) {
    int i = blockIdx.x * blockDim.x + threadIdx.x;
    if (i * 4 >= N_EDGES) return;
    int s0, s1, s2, s3, d0, d1, d2, d3;
    if (g_idx64) {
        const longlong2* ps = (const longlong2*)(const long long*)ei;
        const longlong2* pd = (const longlong2*)((const long long*)ei + N_EDGES);
        longlong2 sv0 = ps[2 * i], sv1 = ps[2 * i + 1];
        longlong2 dv0 = pd[2 * i], dv1 = pd[2 * i + 1];
        s0 = (int)sv0.x; s1 = (int)sv0.y; s2 = (int)sv1.x; s3 = (int)sv1.y;
        d0 = (int)dv0.x; d1 = (int)dv0.y; d2 = (int)dv1.x; d3 = (int)dv1.y;
    } else {
        int4 sv = ((const int4*)(const int*)ei)[i];
        int4 dv = ((const int4*)((const int*)ei + N_EDGES))[i];
        s0 = sv.x; s1 = sv.y; s2 = sv.z; s3 = sv.w;
        d0 = dv.x; d1 = dv.y; d2 = dv.z; d3 = dv.w;
    }
    g_csr_src[atomicAdd(&g_cursor[d0], 1)] = s0;
    g_csr_src[atomicAdd(&g_cursor[d1], 1)] = s1;
    g_csr_src[atomicAdd(&g_cursor[d2], 1)] = s2;
    g_csr_src[atomicAdd(&g_cursor[d3], 1)] = s3;
}

// ======================= CSR gather-mean from fp16: one warp per node =======
__global__ void __launch_bounds__(256)
gather_kernel(const __half* __restrict__ feat,
              __nv_bfloat16* __restrict__ agghi, __nv_bfloat16* __restrict__ agglo) {
    int node = (blockIdx.x * blockDim.x + threadIdx.x) >> 5;
    int lane = threadIdx.x & 31;
    if (node >= N_NODES) return;
    int e = g_off[node];
    const int end = g_off[node + 1];
    float4 acc = make_float4(0.f, 0.f, 0.f, 0.f);
#define ACC_H(v) do { \
        __half2 p0 = *(__half2*)&(v).x, p1 = *(__half2*)&(v).y; \
        float2 f0 = __half22float2(p0), f1 = __half22float2(p1); \
        acc.x += f0.x; acc.y += f0.y; acc.z += f1.x; acc.w += f1.y; } while (0)
    for (; e + 4 <= end; e += 4) {
        int i0 = __ldg(&g_csr_src[e]);
        int i1 = __ldg(&g_csr_src[e + 1]);
        int i2 = __ldg(&g_csr_src[e + 2]);
        int i3 = __ldg(&g_csr_src[e + 3]);
        uint2 v0 = *(const uint2*)(feat + (size_t)i0 * C + lane * 4);
        uint2 v1 = *(const uint2*)(feat + (size_t)i1 * C + lane * 4);
        uint2 v2 = *(const uint2*)(feat + (size_t)i2 * C + lane * 4);
        uint2 v3 = *(const uint2*)(feat + (size_t)i3 * C + lane * 4);
        ACC_H(v0); ACC_H(v1); ACC_H(v2); ACC_H(v3);
    }
    for (; e < end; ++e) {
        int s = __ldg(&g_csr_src[e]);
        uint2 v = *(const uint2*)(feat + (size_t)s * C + lane * 4);
        ACC_H(v);
    }
#undef ACC_H
    float s = g_deg_inv[node];
    acc.x *= s; acc.y *= s; acc.z *= s; acc.w *= s;
    uint2 h, l;
    h.x = split_pack_hi(acc.x, acc.y, l.x);
    h.y = split_pack_hi(acc.z, acc.w, l.y);
    size_t o = (size_t)node * C + lane * 4;
    *(uint2*)(agghi + o) = h;
    *(uint2*)(agglo + o) = l;
}

// ======================= HMMA SAGE GEMM =======================
#define A_STRIDE 72
#define B_STRIDE 136
#define SM_AH 0
#define SM_AL (128 * A_STRIDE * 2)
#define SM_BH (2 * 128 * A_STRIDE * 2)
#define SM_BL (2 * 128 * A_STRIDE * 2 + 64 * B_STRIDE * 2)
#define SM_TOTAL (2 * 128 * A_STRIDE * 2 + 2 * 64 * B_STRIDE * 2)  // 71680 B

__global__ void __launch_bounds__(256)
sage_gemm_mma(const __nv_bfloat16* __restrict__ agghi, const __nv_bfloat16* __restrict__ agglo,
              const __nv_bfloat16* __restrict__ xhi, const __nv_bfloat16* __restrict__ xlo,
              const __nv_bfloat16* __restrict__ Bhi, const __nv_bfloat16* __restrict__ Blo,
              const float* __restrict__ bias, __half* __restrict__ outf16,
              __nv_bfloat16* __restrict__ outhi, __nv_bfloat16* __restrict__ outlo) {
    extern __shared__ unsigned char smem[];
    const uint32_t sbase = smem_u32(smem);
    const int t = threadIdx.x;
    const int wid = t >> 5, lane = t & 31;
    const int warp_m = wid >> 2;
    const int warp_n = wid & 3;
    const int rowBase = blockIdx.x * 128;

    float acc[4][4][4];
#pragma unroll
    for (int i = 0; i < 4; i++)
#pragma unroll
        for (int j = 0; j < 4; j++)
#pragma unroll
            for (int r = 0; r < 4; r++) acc[i][j][r] = 0.f;

    const int a_row = warp_m * 64 + (lane & 15);
    const int a_col = (lane >> 4) * 8;
    const int b_row = (lane & 7) + (lane & 8);
    const int b_col = warp_n * 32 + (lane >> 4) * 8;

    for (int chunk = 0; chunk < 4; ++chunk) {
        const int k0 = chunk * 64;
        const bool isAgg = (chunk < 2);
        const __nv_bfloat16* shi = isAgg ? agghi : xhi;
        const __nv_bfloat16* slo = isAgg ? agglo : xlo;
        const int koff = isAgg ? k0 : (k0 - 128);

#pragma unroll
        for (int it = 0; it < 8; ++it) {
            int idx = it * 256 + t;
            int split = idx >> 10;
            int rem = idx & 1023;
            int row = rem >> 3;
            int q = rem & 7;
            int gm = rowBase + row;
            const __nv_bfloat16* g = split ? slo : shi;
            uint4 v = make_uint4(0u, 0u, 0u, 0u);
            if (gm < N_NODES) v = *(const uint4*)(g + (size_t)gm * C + koff + q * 8);
            uint32_t off = (split ? SM_AL : SM_AH) + (uint32_t)(row * A_STRIDE + q * 8) * 2;
            *(uint4*)(smem + off) = v;
        }
#pragma unroll
        for (int it = 0; it < 8; ++it) {
            int idx = it * 256 + t;
            int split = idx >> 10;
            int rem = idx & 1023;
            int r = rem >> 4;
            int c8 = (rem & 15) * 8;
            const __nv_bfloat16* g = split ? Blo : Bhi;
            uint4 v = *(const uint4*)(g + (size_t)(k0 + r) * 128 + c8);
            uint32_t off = (split ? SM_BL : SM_BH) + (uint32_t)(r * B_STRIDE + c8) * 2;
            *(uint4*)(smem + off) = v;
        }
        __syncthreads();

#pragma unroll
        for (int ks = 0; ks < 4; ++ks) {
            const int kk = ks * 16;
            uint32_t ah[4][4], al[4][4], bh[4][2], bl[4][2];
#pragma unroll
            for (int i = 0; i < 4; ++i) {
                uint32_t addr = sbase + SM_AH +
                    (uint32_t)((a_row + i * 16) * A_STRIDE + kk + a_col) * 2;
                ldsm_x4(ah[i][0], ah[i][1], ah[i][2], ah[i][3], addr);
                ldsm_x4(al[i][0], al[i][1], al[i][2], al[i][3], addr + (SM_AL - SM_AH));
            }
#pragma unroll
            for (int jj = 0; jj < 2; ++jj) {
                uint32_t addr = sbase + SM_BH +
                    (uint32_t)((kk + b_row) * B_STRIDE + b_col + jj * 16) * 2;
                ldsm_x4_t(bh[jj * 2][0], bh[jj * 2][1], bh[jj * 2 + 1][0], bh[jj * 2 + 1][1], addr);
                ldsm_x4_t(bl[jj * 2][0], bl[jj * 2][1], bl[jj * 2 + 1][0], bl[jj * 2 + 1][1],
                          addr + (SM_BL - SM_BH));
            }
#pragma unroll
            for (int i = 0; i < 4; ++i)
#pragma unroll
                for (int j = 0; j < 4; ++j) {
                    mma_bf16(acc[i][j], ah[i], bh[j]);
                    mma_bf16(acc[i][j], ah[i], bl[j]);
                    mma_bf16(acc[i][j], al[i], bh[j]);
                }
        }
        __syncthreads();
    }

    const int er = lane >> 2;
    const int ec = (lane & 3) * 2;
#pragma unroll
    for (int i = 0; i < 4; ++i) {
        int gm0 = rowBase + warp_m * 64 + i * 16 + er;
#pragma unroll
        for (int j = 0; j < 4; ++j) {
            int col = warp_n * 32 + j * 8 + ec;
            float b0 = bias[col], b1 = bias[col + 1];
#pragma unroll
            for (int half = 0; half < 2; ++half) {
                int gm = gm0 + half * 8;
                if (gm < N_NODES) {
                    float ox = fmaxf(acc[i][j][half * 2 + 0] + b0, 0.f);
                    float oy = fmaxf(acc[i][j][half * 2 + 1] + b1, 0.f);
                    if (outf16) {
                        __half2 o2 = __floats2half2_rn(ox, oy);
                        *(uint32_t*)(outf16 + (size_t)gm * C + col) = *(uint32_t*)&o2;
                    }
                    uint32_t lw, hw = split_pack_hi(ox, oy, lw);
                    *(uint32_t*)(outhi + (size_t)gm * C + col) = hw;
                    *(uint32_t*)(outlo + (size_t)gm * C + col) = lw;
                }
            }
        }
    }
}

// ======================= HMMA classifier =======================
#define CB_STRIDE 72
#define CSM_AH 0
#define CSM_AL (128 * A_STRIDE * 2)
#define CSM_BH (2 * 128 * A_STRIDE * 2)
#define CSM_BL (2 * 128 * A_STRIDE * 2 + 64 * CB_STRIDE * 2)
#define CSM_TOTAL (2 * 128 * A_STRIDE * 2 + 2 * 64 * CB_STRIDE * 2)  // 55296 B

__global__ void __launch_bounds__(256)
cls_mma(const __nv_bfloat16* __restrict__ hhi, const __nv_bfloat16* __restrict__ hlo,
        const float* __restrict__ bc, float* __restrict__ out) {
    extern __shared__ unsigned char smem[];
    const uint32_t sbase = smem_u32(smem);
    const int t = threadIdx.x;
    const int wid = t >> 5, lane = t & 31;
    const int warp_m = wid >> 2;
    const int warp_n = wid & 3;
    const int rowBase = blockIdx.x * 128;

    float acc[4][2][4];
#pragma unroll
    for (int i = 0; i < 4; i++)
#pragma unroll
        for (int j = 0; j < 2; j++)
#pragma unroll
            for (int r = 0; r < 4; r++) acc[i][j][r] = 0.f;

    const int a_row = warp_m * 64 + (lane & 15);
    const int a_col = (lane >> 4) * 8;
    const int b_row = (lane & 7) + (lane & 8);
    const int b_col = warp_n * 16 + (lane >> 4) * 8;

    for (int chunk = 0; chunk < 2; ++chunk) {
        const int k0 = chunk * 64;
#pragma unroll
        for (int it = 0; it < 8; ++it) {
            int idx = it * 256 + t;
            int split = idx >> 10;
            int rem = idx & 1023;
            int row = rem >> 3;
            int q = rem & 7;
            int gm = rowBase + row;
            const __nv_bfloat16* g = split ? hlo : hhi;
            uint4 v = make_uint4(0u, 0u, 0u, 0u);
            if (gm < N_NODES) v = *(const uint4*)(g + (size_t)gm * C + k0 + q * 8);
            uint32_t off = (split ? CSM_AL : CSM_AH) + (uint32_t)(row * A_STRIDE + q * 8) * 2;
            *(uint4*)(smem + off) = v;
        }
#pragma unroll
        for (int it = 0; it < 4; ++it) {
            int idx = it * 256 + t;
            int split = idx >> 9;
            int rem = idx & 511;
            int r = rem >> 3;
            int c8 = (rem & 7) * 8;
            const __nv_bfloat16* g = split ? g_Wclo : g_Wchi;
            uint4 v = *(const uint4*)(g + (size_t)(k0 + r) * 64 + c8);
            uint32_t off = (split ? CSM_BL : CSM_BH) + (uint32_t)(r * CB_STRIDE + c8) * 2;
            *(uint4*)(smem + off) = v;
        }
        __syncthreads();

#pragma unroll
        for (int ks = 0; ks < 4; ++ks) {
            const int kk = ks * 16;
            uint32_t ah[4][4], al[4][4], bh[2][2], bl[2][2];
#pragma unroll
            for (int i = 0; i < 4; ++i) {
                uint32_t addr = sbase + CSM_AH +
                    (uint32_t)((a_row + i * 16) * A_STRIDE + kk + a_col) * 2;
                ldsm_x4(ah[i][0], ah[i][1], ah[i][2], ah[i][3], addr);
                ldsm_x4(al[i][0], al[i][1], al[i][2], al[i][3], addr + (CSM_AL - CSM_AH));
            }
            {
                uint32_t addr = sbase + CSM_BH +
                    (uint32_t)((kk + b_row) * CB_STRIDE + b_col) * 2;
                ldsm_x4_t(bh[0][0], bh[0][1], bh[1][0], bh[1][1], addr);
                ldsm_x4_t(bl[0][0], bl[0][1], bl[1][0], bl[1][1], addr + (CSM_BL - CSM_BH));
            }
#pragma unroll
            for (int i = 0; i < 4; ++i)
#pragma unroll
                for (int j = 0; j < 2; ++j) {
                    mma_bf16(acc[i][j], ah[i], bh[j]);
                    mma_bf16(acc[i][j], ah[i], bl[j]);
                    mma_bf16(acc[i][j], al[i], bh[j]);
                }
        }
        __syncthreads();
    }

    const int er = lane >> 2;
    const int ec = (lane & 3) * 2;
#pragma unroll
    for (int i = 0; i < 4; ++i) {
        int gm0 = rowBase + warp_m * 64 + i * 16 + er;
#pragma unroll
        for (int j = 0; j < 2; ++j) {
            int col = warp_n * 16 + j * 8 + ec;
            if (col >= NCLS) continue;
            float b0 = bc[col], b1 = bc[col + 1];
#pragma unroll
            for (int half = 0; half < 2; ++half) {
                int gm = gm0 + half * 8;
                if (gm < N_NODES) {
                    float2 o;
                    o.x = acc[i][j][half * 2 + 0] + b0;
                    o.y = acc[i][j][half * 2 + 1] + b1;
                    *(float2*)(out + (size_t)gm * NCLS + col) = o;
                }
            }
        }
    }
}

// ======================= launch =======================
extern "C" void kernel_launch(void* const* d_in, const int* in_sizes, int n_in,
                              void* d_out, int out_size) {
    (void)in_sizes; (void)n_in; (void)out_size;
    const float* x   = (const float*)d_in[0];
    const void*  ei  = d_in[1];
    const float* Wl1 = (const float*)d_in[2];
    const float* Wr1 = (const float*)d_in[3];
    const float* b1  = (const float*)d_in[4];
    const float* Wl2 = (const float*)d_in[5];
    const float* Wr2 = (const float*)d_in[6];
    const float* b2  = (const float*)d_in[7];
    const float* Wc  = (const float*)d_in[8];
    const float* bc  = (const float*)d_in[9];
    float* out = (float*)d_out;

    __nv_bfloat16 *agghi, *agglo, *xhi, *xlo, *h1hi, *h1lo;
    cudaGetSymbolAddress((void**)&agghi, g_agg_hi);
    cudaGetSymbolAddress((void**)&agglo, g_agg_lo);
    cudaGetSymbolAddress((void**)&xhi, g_x_hi);
    cudaGetSymbolAddress((void**)&xlo, g_x_lo);
    cudaGetSymbolAddress((void**)&h1hi, g_h1_hi);
    cudaGetSymbolAddress((void**)&h1lo, g_h1_lo);
    __half *xf16, *h1f16;
    cudaGetSymbolAddress((void**)&xf16, g_x_f16);
    cudaGetSymbolAddress((void**)&h1f16, g_h1_f16);
    __nv_bfloat16 *b1hi, *b1lo, *b2hi, *b2lo;
    cudaGetSymbolAddress((void**)&b1hi, g_B1hi);
    cudaGetSymbolAddress((void**)&b1lo, g_B1lo);
    cudaGetSymbolAddress((void**)&b2hi, g_B2hi);
    cudaGetSymbolAddress((void**)&b2lo, g_B2lo);

    cudaFuncSetAttribute(sage_gemm_mma, cudaFuncAttributeMaxDynamicSharedMemorySize, SM_TOTAL);
    cudaFuncSetAttribute(cls_mma, cudaFuncAttributeMaxDynamicSharedMemorySize, CSM_TOTAL);

    const int nBlocks = (N_NODES + 127) / 128;            // 391
    const int gatherBlocks = (N_NODES * 32 + 255) / 256;  // 6250
    const int edge4Blocks = (N_EDGES / 4 + 255) / 256;    // 782
    const int prepBlocks = (N_NODES * C / 4 + 255) / 256; // 6250

    prep_all<<<prepBlocks, 256>>>((const unsigned int*)ei, x, Wl1, Wr1, Wl2, Wr2, Wc);

    // CSR build
    deg_kernel<<<edge4Blocks, 256>>>(ei);
    scan_part_kernel<<<NB_SCAN, 256>>>();
    scan_finish_kernel<<<NB_SCAN, 256>>>();
    csrfill_kernel<<<edge4Blocks, 256>>>(ei);

    // layer 1
    gather_kernel<<<gatherBlocks, 256>>>(xf16, agghi, agglo);
    sage_gemm_mma<<<nBlocks, 256, SM_TOTAL>>>(agghi, agglo, xhi, xlo,
                                              b1hi, b1lo, b1, h1f16, h1hi, h1lo);

    // layer 2 (h2 splits land in the retired x-split buffers)
    gather_kernel<<<gatherBlocks, 256>>>(h1f16, agghi, agglo);
    sage_gemm_mma<<<nBlocks, 256, SM_TOTAL>>>(agghi, agglo, h1hi, h1lo,
                                              b2hi, b2lo, b2, (__half*)0, xhi, xlo);

    // classifier
    cls_mma<<<nBlocks, 256, CSM_TOTAL>>>(xhi, xlo, bc, out);
}

// round 9
// speedup vs baseline: 3.8244x; 1.4769x over previous
#include <cuda_runtime.h>
#include <cuda_bf16.h>
#include <cuda_fp16.h>
#include <cstdint>

#define N_NODES 50000
#define N_EDGES 800000
#define C 128
#define NCLS 40
#define NB_SCAN ((N_NODES + 255) / 256)   // 196

// ======================= scratch (no allocation allowed) ====================
__device__ __align__(256) float g_deg_inv[N_NODES];
__device__ __align__(256) int   g_deg[N_NODES];
__device__ __align__(256) int   g_off[N_NODES + 1];
__device__ __align__(256) int   g_cursor[N_NODES];
__device__ __align__(256) int   g_csr_src[N_EDGES];
__device__ __align__(256) int   g_bsum[NB_SCAN];
// fp16 activation images (g_x_f16 is reused for h2 after GEMM-1 consumes x)
__device__ __align__(256) __half g_x_f16[N_NODES * C];
__device__ __align__(256) __half g_h1_f16[N_NODES * C];
__device__ __align__(256) __half g_agg_f16[N_NODES * C];
// Weight images: fp16 hi/lo 2-split (22 mantissa bits ~ exact)
__device__ __align__(256) __half g_B1hi[256 * 128];
__device__ __align__(256) __half g_B1lo[256 * 128];
__device__ __align__(256) __half g_B2hi[256 * 128];
__device__ __align__(256) __half g_B2lo[256 * 128];
__device__ __align__(256) __half g_Wchi[128 * 64];
__device__ __align__(256) __half g_Wclo[128 * 64];
__device__ int g_idx64;

// ======================= helpers =======================
__device__ __forceinline__ uint32_t smem_u32(const void* p) {
    uint32_t a;
    asm("{ .reg .u64 t; cvta.to.shared.u64 t, %1; cvt.u32.u64 %0, t; }"
        : "=r"(a) : "l"(p));
    return a;
}
__device__ __forceinline__ void ldsm_x4(uint32_t& r0, uint32_t& r1,
                                        uint32_t& r2, uint32_t& r3, uint32_t addr) {
    asm volatile("ldmatrix.sync.aligned.m8n8.x4.shared.b16 {%0,%1,%2,%3}, [%4];"
                 : "=r"(r0), "=r"(r1), "=r"(r2), "=r"(r3) : "r"(addr));
}
__device__ __forceinline__ void ldsm_x4_t(uint32_t& r0, uint32_t& r1,
                                          uint32_t& r2, uint32_t& r3, uint32_t addr) {
    asm volatile("ldmatrix.sync.aligned.m8n8.x4.trans.shared.b16 {%0,%1,%2,%3}, [%4];"
                 : "=r"(r0), "=r"(r1), "=r"(r2), "=r"(r3) : "r"(addr));
}
__device__ __forceinline__ void mma_f16(float* c, const uint32_t* a, const uint32_t* b) {
    asm volatile(
        "mma.sync.aligned.m16n8k16.row.col.f32.f16.f16.f32 "
        "{%0,%1,%2,%3}, {%4,%5,%6,%7}, {%8,%9}, {%0,%1,%2,%3};"
        : "+f"(c[0]), "+f"(c[1]), "+f"(c[2]), "+f"(c[3])
        : "r"(a[0]), "r"(a[1]), "r"(a[2]), "r"(a[3]), "r"(b[0]), "r"(b[1]));
}
// block-wide inclusive scan of one int per thread (256 threads, shfl-based)
__device__ __forceinline__ int block_incl_scan(int v, int* wsum /*[8]*/) {
    int lane = threadIdx.x & 31, w = threadIdx.x >> 5;
#pragma unroll
    for (int off = 1; off < 32; off <<= 1) {
        int u = __shfl_up_sync(0xffffffffu, v, off);
        if (lane >= off) v += u;
    }
    if (lane == 31) wsum[w] = v;
    __syncthreads();
    if (w == 0) {
        int s = (lane < 8) ? wsum[lane] : 0;
#pragma unroll
        for (int off = 1; off < 8; off <<= 1) {
            int u = __shfl_up_sync(0xffffffffu, s, off);
            if (lane >= off) s += u;
        }
        if (lane < 8) wsum[lane] = s;
    }
    __syncthreads();
    if (w > 0) v += wsum[w - 1];
    return v;
}

// ======================= fused prep: detect + deg-zero + weights + x-f16 ====
__global__ void __launch_bounds__(256)
prep_all(const unsigned int* __restrict__ ei,
         const float* __restrict__ x,
         const float* __restrict__ Wl1, const float* __restrict__ Wr1,
         const float* __restrict__ Wl2, const float* __restrict__ Wr2,
         const float* __restrict__ Wc) {
    int i = blockIdx.x * blockDim.x + threadIdx.x;
    if (i == 0) {
        int zeros = 0;
        for (int j = 1; j < 128; j += 2) zeros += (ei[j] == 0u);
        g_idx64 = (zeros >= 32) ? 1 : 0;
    }
    if (i < N_NODES) g_deg[i] = 0;
    if (i < 2 * 256 * 128) {
        int layer = i >> 15;
        int rem = i & 32767;
        int k = rem >> 7;
        int n = rem & 127;
        const float* W = (layer == 0) ? ((k < 128) ? Wl1 : Wr1) : ((k < 128) ? Wl2 : Wr2);
        float v = W[(k & 127) * 128 + n];
        __half hi = __float2half_rn(v);
        __half lo = __float2half_rn(v - __half2float(hi));
        (layer ? g_B2hi : g_B1hi)[k * 128 + n] = hi;
        (layer ? g_B2lo : g_B1lo)[k * 128 + n] = lo;
    } else if (i < 2 * 256 * 128 + 128 * 64) {
        int rem = i - 2 * 256 * 128;
        int k = rem >> 6;
        int n = rem & 63;
        float v = (n < NCLS) ? Wc[k * NCLS + n] : 0.f;
        __half hi = __float2half_rn(v);
        __half lo = __float2half_rn(v - __half2float(hi));
        g_Wchi[k * 64 + n] = hi;
        g_Wclo[k * 64 + n] = lo;
    }
    if (i < N_NODES * C / 4) {
        float4 v = ((const float4*)x)[i];
        __half2 f0 = __floats2half2_rn(v.x, v.y);
        __half2 f1 = __floats2half2_rn(v.z, v.w);
        uint2 f;
        f.x = *(uint32_t*)&f0;
        f.y = *(uint32_t*)&f1;
        ((uint2*)g_x_f16)[i] = f;
    }
}

// ======================= degree histogram, 4 edges/thread ====================
__global__ void deg_kernel(const void* ei) {
    int i = blockIdx.x * blockDim.x + threadIdx.x;
    if (i * 4 >= N_EDGES) return;
    int d0, d1, d2, d3;
    if (g_idx64) {
        const longlong2* p = (const longlong2*)((const long long*)ei + N_EDGES);
        longlong2 v0 = p[2 * i], v1 = p[2 * i + 1];
        d0 = (int)v0.x; d1 = (int)v0.y; d2 = (int)v1.x; d3 = (int)v1.y;
    } else {
        int4 v = ((const int4*)((const int*)ei + N_EDGES))[i];
        d0 = v.x; d1 = v.y; d2 = v.z; d3 = v.w;
    }
    atomicAdd(&g_deg[d0], 1);
    atomicAdd(&g_deg[d1], 1);
    atomicAdd(&g_deg[d2], 1);
    atomicAdd(&g_deg[d3], 1);
}

// ---- scan phase 1: per-block sums ----
__global__ void __launch_bounds__(256) scan_part_kernel() {
    int t = threadIdx.x;
    int i = blockIdx.x * 256 + t;
    int v = (i < N_NODES) ? g_deg[i] : 0;
#pragma unroll
    for (int off = 16; off > 0; off >>= 1) v += __shfl_down_sync(0xffffffffu, v, off);
    __shared__ int wsum[8];
    if ((t & 31) == 0) wsum[t >> 5] = v;
    __syncthreads();
    if (t == 0) {
        int s = 0;
#pragma unroll
        for (int w = 0; w < 8; w++) s += wsum[w];
        g_bsum[blockIdx.x] = s;
    }
}
// ---- scan phase 2: each block re-scans the 196 block sums + its slice ----
__global__ void __launch_bounds__(256) scan_finish_kernel() {
    __shared__ int ws1[8];
    __shared__ int ws2[8];
    __shared__ int blockPreSh;
    int t = threadIdx.x;
    int bv = (t < NB_SCAN) ? g_bsum[t] : 0;
    int binc = block_incl_scan(bv, ws1);
    if (t == blockIdx.x) blockPreSh = binc - bv;  // exclusive prefix of this block
    __syncthreads();
    int blockPre = blockPreSh;
    int i = blockIdx.x * 256 + t;
    int d = (i < N_NODES) ? g_deg[i] : 0;
    int inc = block_incl_scan(d, ws2);
    if (i < N_NODES) {
        int o = blockPre + inc - d;
        g_off[i] = o;
        g_cursor[i] = o;
        g_deg_inv[i] = (d > 0) ? (1.0f / (float)d) : 0.0f;
    }
    if (blockIdx.x == 0 && t == 0) g_off[N_NODES] = N_EDGES;
}

// CSR fill, 4 edges/thread
__global__ void csrfill_kernel(const void* __restrict__ ei) {
    int i = blockIdx.x * blockDim.x + threadIdx.x;
    if (i * 4 >= N_EDGES) return;
    int s0, s1, s2, s3, d0, d1, d2, d3;
    if (g_idx64) {
        const longlong2* ps = (const longlong2*)(const long long*)ei;
        const longlong2* pd = (const longlong2*)((const long long*)ei + N_EDGES);
        longlong2 sv0 = ps[2 * i], sv1 = ps[2 * i + 1];
        longlong2 dv0 = pd[2 * i], dv1 = pd[2 * i + 1];
        s0 = (int)sv0.x; s1 = (int)sv0.y; s2 = (int)sv1.x; s3 = (int)sv1.y;
        d0 = (int)dv0.x; d1 = (int)dv0.y; d2 = (int)dv1.x; d3 = (int)dv1.y;
    } else {
        int4 sv = ((const int4*)(const int*)ei)[i];
        int4 dv = ((const int4*)((const int*)ei + N_EDGES))[i];
        s0 = sv.x; s1 = sv.y; s2 = sv.z; s3 = sv.w;
        d0 = dv.x; d1 = dv.y; d2 = dv.z; d3 = dv.w;
    }
    g_csr_src[atomicAdd(&g_cursor[d0], 1)] = s0;
    g_csr_src[atomicAdd(&g_cursor[d1], 1)] = s1;
    g_csr_src[atomicAdd(&g_cursor[d2], 1)] = s2;
    g_csr_src[atomicAdd(&g_cursor[d3], 1)] = s3;
}

// ======================= CSR gather-mean (fp16 in, fp16 out) =================
__global__ void __launch_bounds__(256)
gather_kernel(const __half* __restrict__ feat, __half* __restrict__ agg) {
    int node = (blockIdx.x * blockDim.x + threadIdx.x) >> 5;
    int lane = threadIdx.x & 31;
    if (node >= N_NODES) return;
    int e = g_off[node];
    const int end = g_off[node + 1];
    float4 acc = make_float4(0.f, 0.f, 0.f, 0.f);
#define ACC_H(v) do { \
        __half2 p0 = *(__half2*)&(v).x, p1 = *(__half2*)&(v).y; \
        float2 f0 = __half22float2(p0), f1 = __half22float2(p1); \
        acc.x += f0.x; acc.y += f0.y; acc.z += f1.x; acc.w += f1.y; } while (0)
    for (; e + 4 <= end; e += 4) {
        int i0 = __ldg(&g_csr_src[e]);
        int i1 = __ldg(&g_csr_src[e + 1]);
        int i2 = __ldg(&g_csr_src[e + 2]);
        int i3 = __ldg(&g_csr_src[e + 3]);
        uint2 v0 = *(const uint2*)(feat + (size_t)i0 * C + lane * 4);
        uint2 v1 = *(const uint2*)(feat + (size_t)i1 * C + lane * 4);
        uint2 v2 = *(const uint2*)(feat + (size_t)i2 * C + lane * 4);
        uint2 v3 = *(const uint2*)(feat + (size_t)i3 * C + lane * 4);
        ACC_H(v0); ACC_H(v1); ACC_H(v2); ACC_H(v3);
    }
    for (; e < end; ++e) {
        int s = __ldg(&g_csr_src[e]);
        uint2 v = *(const uint2*)(feat + (size_t)s * C + lane * 4);
        ACC_H(v);
    }
#undef ACC_H
    float s = g_deg_inv[node];
    __half2 o0 = __floats2half2_rn(acc.x * s, acc.y * s);
    __half2 o1 = __floats2half2_rn(acc.z * s, acc.w * s);
    uint2 o;
    o.x = *(uint32_t*)&o0;
    o.y = *(uint32_t*)&o1;
    *(uint2*)(agg + (size_t)node * C + lane * 4) = o;
}

// ======================= HMMA SAGE GEMM (2-term fp16) ========================
// out = relu([agg | x] @ (Bh+Bl) + bias). A plain fp16, B fp16 hi/lo.
// BM=128, BN=128, BK=64, 8 warps (2 m x 4 n), warp tile 64x32.
#define A_STRIDE 72
#define B_STRIDE 136
#define SM_A  0
#define SM_BH (128 * A_STRIDE * 2)
#define SM_BL (128 * A_STRIDE * 2 + 64 * B_STRIDE * 2)
#define SM_TOTAL (128 * A_STRIDE * 2 + 2 * 64 * B_STRIDE * 2)  // 53248 B

__global__ void __launch_bounds__(256)
sage_gemm_mma(const __half* __restrict__ agg, const __half* __restrict__ xin,
              const __half* __restrict__ Bhi, const __half* __restrict__ Blo,
              const float* __restrict__ bias, __half* __restrict__ outf16) {
    extern __shared__ unsigned char smem[];
    const uint32_t sbase = smem_u32(smem);
    const int t = threadIdx.x;
    const int wid = t >> 5, lane = t & 31;
    const int warp_m = wid >> 2;
    const int warp_n = wid & 3;
    const int rowBase = blockIdx.x * 128;

    float acc[4][4][4];
#pragma unroll
    for (int i = 0; i < 4; i++)
#pragma unroll
        for (int j = 0; j < 4; j++)
#pragma unroll
            for (int r = 0; r < 4; r++) acc[i][j][r] = 0.f;

    const int a_row = warp_m * 64 + (lane & 15);
    const int a_col = (lane >> 4) * 8;
    const int b_row = (lane & 7) + (lane & 8);
    const int b_col = warp_n * 32 + (lane >> 4) * 8;

    for (int chunk = 0; chunk < 4; ++chunk) {
        const int k0 = chunk * 64;
        const bool isAgg = (chunk < 2);
        const __half* src = isAgg ? agg : xin;
        const int koff = isAgg ? k0 : (k0 - 128);

        // A fill: 128 rows x 64 k fp16 = 1024 uint4
#pragma unroll
        for (int it = 0; it < 4; ++it) {
            int idx = it * 256 + t;
            int row = idx >> 3;
            int q = idx & 7;
            int gm = rowBase + row;
            uint4 v = make_uint4(0u, 0u, 0u, 0u);
            if (gm < N_NODES) v = *(const uint4*)(src + (size_t)gm * C + koff + q * 8);
            uint32_t off = SM_A + (uint32_t)(row * A_STRIDE + q * 8) * 2;
            *(uint4*)(smem + off) = v;
        }
        // B fill: 64 k-rows x 128 n, hi+lo = 2048 uint4
#pragma unroll
        for (int it = 0; it < 8; ++it) {
            int idx = it * 256 + t;
            int split = idx >> 10;
            int rem = idx & 1023;
            int r = rem >> 4;
            int c8 = (rem & 15) * 8;
            const __half* g = split ? Blo : Bhi;
            uint4 v = *(const uint4*)(g + (size_t)(k0 + r) * 128 + c8);
            uint32_t off = (split ? SM_BL : SM_BH) + (uint32_t)(r * B_STRIDE + c8) * 2;
            *(uint4*)(smem + off) = v;
        }
        __syncthreads();

#pragma unroll
        for (int ks = 0; ks < 4; ++ks) {
            const int kk = ks * 16;
            uint32_t a[4][4], bh[4][2], bl[4][2];
#pragma unroll
            for (int i = 0; i < 4; ++i) {
                uint32_t addr = sbase + SM_A +
                    (uint32_t)((a_row + i * 16) * A_STRIDE + kk + a_col) * 2;
                ldsm_x4(a[i][0], a[i][1], a[i][2], a[i][3], addr);
            }
#pragma unroll
            for (int jj = 0; jj < 2; ++jj) {
                uint32_t addr = sbase + SM_BH +
                    (uint32_t)((kk + b_row) * B_STRIDE + b_col + jj * 16) * 2;
                ldsm_x4_t(bh[jj * 2][0], bh[jj * 2][1], bh[jj * 2 + 1][0], bh[jj * 2 + 1][1], addr);
                ldsm_x4_t(bl[jj * 2][0], bl[jj * 2][1], bl[jj * 2 + 1][0], bl[jj * 2 + 1][1],
                          addr + (SM_BL - SM_BH));
            }
#pragma unroll
            for (int i = 0; i < 4; ++i)
#pragma unroll
                for (int j = 0; j < 4; ++j) {
                    mma_f16(acc[i][j], a[i], bh[j]);
                    mma_f16(acc[i][j], a[i], bl[j]);
                }
        }
        __syncthreads();
    }

    const int er = lane >> 2;
    const int ec = (lane & 3) * 2;
#pragma unroll
    for (int i = 0; i < 4; ++i) {
        int gm0 = rowBase + warp_m * 64 + i * 16 + er;
#pragma unroll
        for (int j = 0; j < 4; ++j) {
            int col = warp_n * 32 + j * 8 + ec;
            float b0 = bias[col], b1 = bias[col + 1];
#pragma unroll
            for (int half = 0; half < 2; ++half) {
                int gm = gm0 + half * 8;
                if (gm < N_NODES) {
                    float ox = fmaxf(acc[i][j][half * 2 + 0] + b0, 0.f);
                    float oy = fmaxf(acc[i][j][half * 2 + 1] + b1, 0.f);
                    __half2 o2 = __floats2half2_rn(ox, oy);
                    *(uint32_t*)(outf16 + (size_t)gm * C + col) = *(uint32_t*)&o2;
                }
            }
        }
    }
}

// ======================= HMMA classifier (2-term fp16) =======================
#define CB_STRIDE 72
#define CSM_A  0
#define CSM_BH (128 * A_STRIDE * 2)
#define CSM_BL (128 * A_STRIDE * 2 + 64 * CB_STRIDE * 2)
#define CSM_TOTAL (128 * A_STRIDE * 2 + 2 * 64 * CB_STRIDE * 2)  // 36864 B

__global__ void __launch_bounds__(256)
cls_mma(const __half* __restrict__ h2, const float* __restrict__ bc,
        float* __restrict__ out) {
    extern __shared__ unsigned char smem[];
    const uint32_t sbase = smem_u32(smem);
    const int t = threadIdx.x;
    const int wid = t >> 5, lane = t & 31;
    const int warp_m = wid >> 2;
    const int warp_n = wid & 3;
    const int rowBase = blockIdx.x * 128;

    float acc[4][2][4];
#pragma unroll
    for (int i = 0; i < 4; i++)
#pragma unroll
        for (int j = 0; j < 2; j++)
#pragma unroll
            for (int r = 0; r < 4; r++) acc[i][j][r] = 0.f;

    const int a_row = warp_m * 64 + (lane & 15);
    const int a_col = (lane >> 4) * 8;
    const int b_row = (lane & 7) + (lane & 8);
    const int b_col = warp_n * 16 + (lane >> 4) * 8;

    for (int chunk = 0; chunk < 2; ++chunk) {
        const int k0 = chunk * 64;
        // A fill: 128 rows x 64 k fp16 = 1024 uint4
#pragma unroll
        for (int it = 0; it < 4; ++it) {
            int idx = it * 256 + t;
            int row = idx >> 3;
            int q = idx & 7;
            int gm = rowBase + row;
            uint4 v = make_uint4(0u, 0u, 0u, 0u);
            if (gm < N_NODES) v = *(const uint4*)(h2 + (size_t)gm * C + k0 + q * 8);
            uint32_t off = CSM_A + (uint32_t)(row * A_STRIDE + q * 8) * 2;
            *(uint4*)(smem + off) = v;
        }
        // B fill: 64 k-rows x 64 n, hi+lo = 1024 uint4
#pragma unroll
        for (int it = 0; it < 4; ++it) {
            int idx = it * 256 + t;
            int split = idx >> 9;
            int rem = idx & 511;
            int r = rem >> 3;
            int c8 = (rem & 7) * 8;
            const __half* g = split ? g_Wclo : g_Wchi;
            uint4 v = *(const uint4*)(g + (size_t)(k0 + r) * 64 + c8);
            uint32_t off = (split ? CSM_BL : CSM_BH) + (uint32_t)(r * CB_STRIDE + c8) * 2;
            *(uint4*)(smem + off) = v;
        }
        __syncthreads();

#pragma unroll
        for (int ks = 0; ks < 4; ++ks) {
            const int kk = ks * 16;
            uint32_t a[4][4], bh[2][2], bl[2][2];
#pragma unroll
            for (int i = 0; i < 4; ++i) {
                uint32_t addr = sbase + CSM_A +
                    (uint32_t)((a_row + i * 16) * A_STRIDE + kk + a_col) * 2;
                ldsm_x4(a[i][0], a[i][1], a[i][2], a[i][3], addr);
            }
            {
                uint32_t addr = sbase + CSM_BH +
                    (uint32_t)((kk + b_row) * CB_STRIDE + b_col) * 2;
                ldsm_x4_t(bh[0][0], bh[0][1], bh[1][0], bh[1][1], addr);
                ldsm_x4_t(bl[0][0], bl[0][1], bl[1][0], bl[1][1], addr + (CSM_BL - CSM_BH));
            }
#pragma unroll
            for (int i = 0; i < 4; ++i)
#pragma unroll
                for (int j = 0; j < 2; ++j) {
                    mma_f16(acc[i][j], a[i], bh[j]);
                    mma_f16(acc[i][j], a[i], bl[j]);
                }
        }
        __syncthreads();
    }

    const int er = lane >> 2;
    const int ec = (lane & 3) * 2;
#pragma unroll
    for (int i = 0; i < 4; ++i) {
        int gm0 = rowBase + warp_m * 64 + i * 16 + er;
#pragma unroll
        for (int j = 0; j < 2; ++j) {
            int col = warp_n * 16 + j * 8 + ec;
            if (col >= NCLS) continue;
            float b0 = bc[col], b1 = bc[col + 1];
#pragma unroll
            for (int half = 0; half < 2; ++half) {
                int gm = gm0 + half * 8;
                if (gm < N_NODES) {
                    float2 o;
                    o.x = acc[i][j][half * 2 + 0] + b0;
                    o.y = acc[i][j][half * 2 + 1] + b1;
                    *(float2*)(out + (size_t)gm * NCLS + col) = o;
                }
            }
        }
    }
}

// ======================= launch =======================
extern "C" void kernel_launch(void* const* d_in, const int* in_sizes, int n_in,
                              void* d_out, int out_size) {
    (void)in_sizes; (void)n_in; (void)out_size;
    const float* x   = (const float*)d_in[0];
    const void*  ei  = d_in[1];
    const float* Wl1 = (const float*)d_in[2];
    const float* Wr1 = (const float*)d_in[3];
    const float* b1  = (const float*)d_in[4];
    const float* Wl2 = (const float*)d_in[5];
    const float* Wr2 = (const float*)d_in[6];
    const float* b2  = (const float*)d_in[7];
    const float* Wc  = (const float*)d_in[8];
    const float* bc  = (const float*)d_in[9];
    float* out = (float*)d_out;

    __half *xf16, *h1f16, *aggf16;
    cudaGetSymbolAddress((void**)&xf16, g_x_f16);
    cudaGetSymbolAddress((void**)&h1f16, g_h1_f16);
    cudaGetSymbolAddress((void**)&aggf16, g_agg_f16);
    __half *b1hi, *b1lo, *b2hi, *b2lo;
    cudaGetSymbolAddress((void**)&b1hi, g_B1hi);
    cudaGetSymbolAddress((void**)&b1lo, g_B1lo);
    cudaGetSymbolAddress((void**)&b2hi, g_B2hi);
    cudaGetSymbolAddress((void**)&b2lo, g_B2lo);

    cudaFuncSetAttribute(sage_gemm_mma, cudaFuncAttributeMaxDynamicSharedMemorySize, SM_TOTAL);
    cudaFuncSetAttribute(cls_mma, cudaFuncAttributeMaxDynamicSharedMemorySize, CSM_TOTAL);

    const int nBlocks = (N_NODES + 127) / 128;            // 391
    const int gatherBlocks = (N_NODES * 32 + 255) / 256;  // 6250
    const int edge4Blocks = (N_EDGES / 4 + 255) / 256;    // 782
    const int prepBlocks = (N_NODES * C / 4 + 255) / 256; // 6250

    prep_all<<<prepBlocks, 256>>>((const unsigned int*)ei, x, Wl1, Wr1, Wl2, Wr2, Wc);

    // CSR build
    deg_kernel<<<edge4Blocks, 256>>>(ei);
    scan_part_kernel<<<NB_SCAN, 256>>>();
    scan_finish_kernel<<<NB_SCAN, 256>>>();
    csrfill_kernel<<<edge4Blocks, 256>>>(ei);

    // layer 1
    gather_kernel<<<gatherBlocks, 256>>>(xf16, aggf16);
    sage_gemm_mma<<<nBlocks, 256, SM_TOTAL>>>(aggf16, xf16, b1hi, b1lo, b1, h1f16);

    // layer 2 (h2 fp16 lands in the retired x buffer)
    gather_kernel<<<gatherBlocks, 256>>>(h1f16, aggf16);
    sage_gemm_mma<<<nBlocks, 256, SM_TOTAL>>>(aggf16, h1f16, b2hi, b2lo, b2, xf16);

    // classifier
    cls_mma<<<nBlocks, 256, CSM_TOTAL>>>(xf16, bc, out);
}